// round 12
// baseline (speedup 1.0000x reference)
#include <cuda_runtime.h>
#include <cuda_bf16.h>
#include <math.h>
#include <stdint.h>

#define B_  2
#define S_  2048
#define D_  2048
#define H_  16
#define DK_ 128
#define M_  (B_*S_)   // 4096
#define BH_ (B_*H_)   // 32
#define K2_ 4096      // [hi | lo] dedup layout

// ---------------- scratch (device globals; no allocs allowed) ----------------
__device__ __nv_bfloat16 g_acat0[M_*K2_];  // query split / attn-out split
__device__ __nv_bfloat16 g_acat1[M_*K2_];  // key split
__device__ __nv_bfloat16 g_acat2[M_*K2_];  // value split
__device__ __nv_bfloat16 g_wcat0[D_*K2_];  // wq
__device__ __nv_bfloat16 g_wcat1[D_*K2_];  // wk
__device__ __nv_bfloat16 g_wcat2[D_*K2_];  // wv
__device__ __nv_bfloat16 g_wcat3[D_*K2_];  // wo
__device__ float g_cos[S_*64];
__device__ float g_sin[S_*64];
__device__ __nv_bfloat16 g_qh[BH_*S_*DK_], g_ql[BH_*S_*DK_];
__device__ __nv_bfloat16 g_kh[BH_*S_*DK_], g_kl[BH_*S_*DK_];
__device__ __nv_bfloat16 g_vth[BH_*DK_*S_], g_vtl[BH_*DK_*S_];  // [bh][d][s]

__device__ __forceinline__ uint32_t smem_u32(const void* p) {
    uint32_t a;
    asm("{ .reg .u64 t; cvta.to.shared.u64 t, %1; cvt.u32.u64 %0, t; }" : "=r"(a) : "l"(p));
    return a;
}

#define LDSM4(r0,r1,r2,r3, addr) \
    asm volatile("ldmatrix.sync.aligned.m8n8.x4.shared.b16 {%0,%1,%2,%3}, [%4];" \
        : "=r"(r0), "=r"(r1), "=r"(r2), "=r"(r3) : "r"(addr))

#define MMA16816(d, a, b0v, b1v) \
    asm volatile("mma.sync.aligned.m16n8k16.row.col.f32.bf16.bf16.f32 " \
        "{%0,%1,%2,%3}, {%4,%5,%6,%7}, {%8,%9}, {%0,%1,%2,%3};" \
        : "+f"((d)[0]), "+f"((d)[1]), "+f"((d)[2]), "+f"((d)[3]) \
        : "r"((a)[0]), "r"((a)[1]), "r"((a)[2]), "r"((a)[3]), "r"(b0v), "r"(b1v))

#define CPA16(dst, src) \
    asm volatile("cp.async.cg.shared.global [%0], [%1], 16;" :: "r"(dst), "l"(src))

// ---------------- hi/lo split (all 7 jobs in one launch) ----------------
__device__ __forceinline__ void split_body(
    const float* __restrict__ x, __nv_bfloat16* __restrict__ out, int lb)
{
    int i4 = (lb * 256 + threadIdx.x) * 4;
    int r = i4 >> 11, c = i4 & 2047;
    float4 v = *(const float4*)(x + i4);
    __nv_bfloat16 h0 = __float2bfloat16(v.x), h1 = __float2bfloat16(v.y);
    __nv_bfloat16 h2 = __float2bfloat16(v.z), h3 = __float2bfloat16(v.w);
    __nv_bfloat162 H01, H23, L01, L23;
    H01.x = h0; H01.y = h1; H23.x = h2; H23.y = h3;
    L01.x = __float2bfloat16(v.x - __bfloat162float(h0));
    L01.y = __float2bfloat16(v.y - __bfloat162float(h1));
    L23.x = __float2bfloat16(v.z - __bfloat162float(h2));
    L23.y = __float2bfloat16(v.w - __bfloat162float(h3));
    __nv_bfloat16* row = out + (size_t)r * K2_ + c;
    *(__nv_bfloat162*)(row)            = H01;
    *(__nv_bfloat162*)(row + 2)        = H23;
    *(__nv_bfloat162*)(row + 2048)     = L01;
    *(__nv_bfloat162*)(row + 2048 + 2) = L23;
}

__global__ __launch_bounds__(256) void split_all(
    const float* q, const float* k, const float* v,
    const float* wq, const float* wk, const float* wv, const float* wo,
    __nv_bfloat16* a0, __nv_bfloat16* a1, __nv_bfloat16* a2,
    __nv_bfloat16* w0, __nv_bfloat16* w1, __nv_bfloat16* w2, __nv_bfloat16* w3)
{
    int bx = blockIdx.x;
    if (bx < 8192)        split_body(q, a0, bx);
    else if (bx < 16384)  split_body(k, a1, bx - 8192);
    else if (bx < 24576)  split_body(v, a2, bx - 16384);
    else {
        int t = bx - 24576, z = t >> 12, lb = t & 4095;
        const float* x = z == 0 ? wq : (z == 1 ? wk : (z == 2 ? wv : wo));
        __nv_bfloat16* o = z == 0 ? w0 : (z == 1 ? w1 : (z == 2 ? w2 : w3));
        split_body(x, o, lb);
    }
}

// ---------------- RoPE table ----------------
__global__ __launch_bounds__(256) void rope_table()
{
    int idx = blockIdx.x * blockDim.x + threadIdx.x;
    if (idx >= S_ * 64) return;
    int i = idx & 63;
    int s = idx >> 6;
    float inv = powf(10000.f, -(float)(2 * i) / 128.f);
    float ph  = (float)s * inv;
    g_cos[idx] = cosf(ph);
    g_sin[idx] = sinf(ph);
}

// ---------------- mma.sync GEMM: 3-stage ring, XOR-swizzled 32-col buffers ----
#define BUF_B 8192
#define STAGE_B (4*BUF_B)
#define NSTG 3
#define GEMM_SMEM (NSTG*STAGE_B)      // 98304 B (occ 2)
#define NCH2 64
#define SWX(r, cI) ((uint32_t)((r)*64 + ((((cI) ^ (((r)>>1)&3)) & 3) << 4)))
#define LDE 133

__device__ __forceinline__ void gemm_body(
    const __nv_bfloat16* __restrict__ A, const __nv_bfloat16* __restrict__ Wt,
    const float* __restrict__ bias, int mode, float* __restrict__ C,
    __nv_bfloat16* __restrict__ bho, __nv_bfloat16* __restrict__ blo)
{
    extern __shared__ __nv_bfloat16 sm[];
    const int tid = threadIdx.x;
    const int lane = tid & 31, w = tid >> 5;
    const int wm = (w >> 2) << 6;
    const int wn = (w & 3) << 5;
    const int m0 = blockIdx.y << 7, n0 = blockIdx.x << 7;

    const __nv_bfloat16* Ag = A  + (size_t)m0 * K2_;
    const __nv_bfloat16* Wg = Wt + (size_t)n0 * K2_;

    float acc[4][4][4];
#pragma unroll
    for (int mi = 0; mi < 4; mi++)
#pragma unroll
        for (int ni = 0; ni < 4; ni++)
#pragma unroll
            for (int j = 0; j < 4; j++) acc[mi][ni][j] = 0.f;

    const int r0 = tid >> 2,        cI0 = tid & 3;
    const int r1 = (tid >> 2) + 64, cI1 = tid & 3;
    const uint32_t so0 = SWX(r0, cI0), so1 = SWX(r1, cI1);
    const int e0 = cI0 << 3, e1 = cI1 << 3;
#define LOAD_CHUNK2(stage, chunk) do {                                           \
    uint32_t sb = smem_u32((const char*)sm + (stage) * STAGE_B);                 \
    const size_t off = (size_t)(chunk) * 32;                                     \
    CPA16(sb + so0,            Ag + (size_t)r0*K2_ + off + e0);                  \
    CPA16(sb + so1,            Ag + (size_t)r1*K2_ + off + e1);                  \
    CPA16(sb + BUF_B + so0,    Ag + (size_t)r0*K2_ + 2048 + off + e0);           \
    CPA16(sb + BUF_B + so1,    Ag + (size_t)r1*K2_ + 2048 + off + e1);           \
    CPA16(sb + 2*BUF_B + so0,  Wg + (size_t)r0*K2_ + off + e0);                  \
    CPA16(sb + 2*BUF_B + so1,  Wg + (size_t)r1*K2_ + off + e1);                  \
    CPA16(sb + 3*BUF_B + so0,  Wg + (size_t)r0*K2_ + 2048 + off + e0);           \
    CPA16(sb + 3*BUF_B + so1,  Wg + (size_t)r1*K2_ + 2048 + off + e1);           \
    asm volatile("cp.async.commit_group;" ::: "memory");                         \
} while (0)

    LOAD_CHUNK2(0, 0);
    LOAD_CHUNK2(1, 1);

    for (int c = 0; c < NCH2; c++) {
        const int s = c % NSTG;
        if (c + 1 < NCH2) {
            asm volatile("cp.async.wait_group 1;" ::: "memory");
        } else {
            asm volatile("cp.async.wait_group 0;" ::: "memory");
        }
        __syncthreads();

        if (c + 2 < NCH2) LOAD_CHUNK2((c + 2) % NSTG, c + 2);

        const uint32_t sb = smem_u32((const char*)sm + s * STAGE_B);
#pragma unroll
        for (int ks = 0; ks < 2; ks++) {
            const int kbase = ks << 1;
            uint32_t ah[4][4], al[4][4];
#pragma unroll
            for (int mi = 0; mi < 4; mi++) {
                int r = wm + (mi << 4) + (lane & 15);
                int cI = kbase + (lane >> 4);
                uint32_t off = SWX(r, cI);
                LDSM4(ah[mi][0], ah[mi][1], ah[mi][2], ah[mi][3], sb + off);
                LDSM4(al[mi][0], al[mi][1], al[mi][2], al[mi][3], sb + BUF_B + off);
            }
            uint32_t bh[4][2], bl[4][2];
#pragma unroll
            for (int nb = 0; nb < 2; nb++) {
                int r = wn + (nb << 4) + (lane & 7) + (((lane >> 4) & 1) << 3);
                int cI = kbase + ((lane >> 3) & 1);
                uint32_t off = SWX(r, cI);
                LDSM4(bh[nb*2][0], bh[nb*2][1], bh[nb*2+1][0], bh[nb*2+1][1],
                      sb + 2*BUF_B + off);
                LDSM4(bl[nb*2][0], bl[nb*2][1], bl[nb*2+1][0], bl[nb*2+1][1],
                      sb + 3*BUF_B + off);
            }
#pragma unroll
            for (int mi = 0; mi < 4; mi++)
#pragma unroll
                for (int ni = 0; ni < 4; ni++) {
                    MMA16816(acc[mi][ni], ah[mi], bh[ni][0], bh[ni][1]);
                    MMA16816(acc[mi][ni], ah[mi], bl[ni][0], bl[ni][1]);
                    MMA16816(acc[mi][ni], al[mi], bh[ni][0], bh[ni][1]);
                }
        }
    }

    if (mode == 0) {
#pragma unroll
        for (int mi = 0; mi < 4; mi++) {
#pragma unroll
            for (int half = 0; half < 2; half++) {
                int m = m0 + wm + (mi << 4) + (lane >> 2) + (half << 3);
#pragma unroll
                for (int ni = 0; ni < 4; ni++) {
                    int n = n0 + wn + (ni << 3) + ((lane & 3) << 1);
                    float2 o;
                    o.x = acc[mi][ni][half*2+0] + bias[n];
                    o.y = acc[mi][ni][half*2+1] + bias[n+1];
                    *(float2*)(C + (size_t)m * D_ + n) = o;
                }
            }
        }
        return;
    }

    __syncthreads();
    float* sf = (float*)sm;
#pragma unroll
    for (int mi = 0; mi < 4; mi++)
#pragma unroll
        for (int half = 0; half < 2; half++) {
            int ml = wm + (mi << 4) + (lane >> 2) + (half << 3);
#pragma unroll
            for (int ni = 0; ni < 4; ni++) {
                int nl = wn + (ni << 3) + ((lane & 3) << 1);
                sf[ml*LDE + nl]     = acc[mi][ni][half*2+0] + bias[n0 + nl];
                sf[ml*LDE + nl + 1] = acc[mi][ni][half*2+1] + bias[n0 + nl + 1];
            }
        }
    __syncthreads();

    const int b  = m0 >> 11;
    const int s0 = m0 & (S_ - 1);
    const int h  = n0 >> 7;
    const int bh = b * H_ + h;

    if (mode == 1) {
        for (int idx = tid; idx < 128 * 64; idx += 256) {
            int r = idx >> 6, i = idx & 63;
            int s = s0 + r;
            float x1 = sf[r*LDE + i], x2 = sf[r*LDE + 64 + i];
            float cc = g_cos[(s << 6) + i], sn = g_sin[(s << 6) + i];
            float v1 = x1 * cc - x2 * sn;
            float v2 = x2 * cc + x1 * sn;
            size_t o = (((size_t)bh * S_ + s) << 7) + i;
            __nv_bfloat16 h1 = __float2bfloat16(v1);
            __nv_bfloat16 h2 = __float2bfloat16(v2);
            bho[o]      = h1;
            bho[o + 64] = h2;
            blo[o]      = __float2bfloat16(v1 - __bfloat162float(h1));
            blo[o + 64] = __float2bfloat16(v2 - __bfloat162float(h2));
        }
    } else {
        for (int idx = tid; idx < 128 * 128; idx += 256) {
            int d = idx >> 7, sl = idx & 127;
            float v = sf[sl*LDE + d];
            __nv_bfloat16 hv = __float2bfloat16(v);
            size_t o = ((size_t)bh * DK_ + d) * S_ + s0 + sl;
            bho[o] = hv;
            blo[o] = __float2bfloat16(v - __bfloat162float(hv));
        }
    }
}

__global__ __launch_bounds__(256, 2) void gemm_qkv(
    const __nv_bfloat16* a0, const __nv_bfloat16* a1, const __nv_bfloat16* a2,
    const __nv_bfloat16* w0, const __nv_bfloat16* w1, const __nv_bfloat16* w2,
    const float* b0, const float* b1, const float* b2,
    __nv_bfloat16* qh, __nv_bfloat16* ql,
    __nv_bfloat16* kh, __nv_bfloat16* kl,
    __nv_bfloat16* vth, __nv_bfloat16* vtl)
{
    int z = blockIdx.z;
    const __nv_bfloat16* A = z == 0 ? a0 : (z == 1 ? a1 : a2);
    const __nv_bfloat16* W = z == 0 ? w0 : (z == 1 ? w1 : w2);
    const float* bias = z == 0 ? b0 : (z == 1 ? b1 : b2);
    __nv_bfloat16* bhp = z == 0 ? qh : (z == 1 ? kh : vth);
    __nv_bfloat16* blp = z == 0 ? ql : (z == 1 ? kl : vtl);
    gemm_body(A, W, bias, z == 2 ? 2 : 1, (float*)0, bhp, blp);
}

__global__ __launch_bounds__(256, 2) void gemm_out(
    const __nv_bfloat16* A, const __nv_bfloat16* W, const float* bias, float* C)
{
    gemm_body(A, W, bias, 0, C, (__nv_bfloat16*)0, (__nv_bfloat16*)0);
}

// ---------------- tensor-core causal flash attention (bf16x3) ----------------
// BR=64 q rows, 128 threads (4 warps x 16 rows), BC=32 keys/iter, 2-stage KV.
// smem 110592 B -> 2 CTAs/SM.
#define QLD 136
#define VLD 40
#define oQH 0
#define oQL 8704            // 64*136
#define oKV 17408
// stage: KH 0 (32x136=4352), KL 4352, VH 8704 (128x40=5120), VL 13824
#define stKV 18944
#define ATTN2_SMEM ((oKV + 2*stKV)*2)   // 110592 B

__global__ __launch_bounds__(128, 2) void attn_mma(
    const __nv_bfloat16* __restrict__ gqh, const __nv_bfloat16* __restrict__ gql,
    const __nv_bfloat16* __restrict__ gkh, const __nv_bfloat16* __restrict__ gkl,
    const __nv_bfloat16* __restrict__ gvh, const __nv_bfloat16* __restrict__ gvl,
    __nv_bfloat16* __restrict__ acat)
{
    extern __shared__ __nv_bfloat16 smb[];
    const uint32_t usm = smem_u32(smb);
    const int tid = threadIdx.x;
    const int lane = tid & 31, w = tid >> 5;      // 4 warps
    const int wrow = w << 4;                       // 16 rows per warp
    const int qt = gridDim.x - 1 - blockIdx.x;     // 64-row q tile, heavy first
    const int bh = blockIdx.y;
    const int b  = bh >> 4, h = bh & 15;
    const int nblk = 2 * qt + 2;                   // 32-key blocks
    const float SCL2 = 0.12751743f;                // 1/sqrt(128) * log2(e)

    const size_t qbase = ((size_t)bh * S_ + (size_t)qt * 64) << 7;

    {
#pragma unroll
        for (int i = 0; i < 8; i++) {
            int ch = tid + (i << 7);               // 0..1023
            int r = ch >> 4, c8 = (ch & 15) << 3;
            CPA16(usm + (uint32_t)(oQH + r * QLD + c8) * 2, gqh + qbase + ((size_t)r << 7) + c8);
            CPA16(usm + (uint32_t)(oQL + r * QLD + c8) * 2, gql + qbase + ((size_t)r << 7) + c8);
        }
    }
#define LOAD_KV(stage, jb) do {                                                      \
    uint32_t kvb = oKV + (stage) * stKV;                                             \
    size_t kbase = ((size_t)bh * S_ + (size_t)(jb) * 32) << 7;                       \
    _Pragma("unroll")                                                                \
    for (int i = 0; i < 4; i++) {                                                    \
        int ch = tid + (i << 7);                   /* 0..511 */                      \
        int r = ch >> 4, c8 = (ch & 15) << 3;                                        \
        CPA16(usm + (kvb + r * QLD + c8) * 2,        gkh + kbase + ((size_t)r << 7) + c8); \
        CPA16(usm + (kvb + 4352 + r * QLD + c8) * 2, gkl + kbase + ((size_t)r << 7) + c8); \
    }                                                                                \
    size_t vbase = ((size_t)bh * DK_) * S_ + (size_t)(jb) * 32;                      \
    _Pragma("unroll")                                                                \
    for (int i = 0; i < 4; i++) {                                                    \
        int ch = tid + (i << 7);                   /* 0..511 */                      \
        int r = ch >> 2, c8 = (ch & 3) << 3;                                         \
        CPA16(usm + (kvb + 8704 + r * VLD + c8) * 2,  gvh + vbase + (size_t)r * S_ + c8); \
        CPA16(usm + (kvb + 13824 + r * VLD + c8) * 2, gvl + vbase + (size_t)r * S_ + c8); \
    }                                                                                \
    asm volatile("cp.async.commit_group;" ::: "memory");                             \
} while (0)

    LOAD_KV(0, 0);
    LOAD_KV(1, 1);

    float oa[16][4];
#pragma unroll
    for (int nt = 0; nt < 16; nt++)
#pragma unroll
        for (int j = 0; j < 4; j++) oa[nt][j] = 0.f;
    float m0r = -1e30f, m1r = -1e30f, l0r = 0.f, l1r = 0.f;

    const int grow0 = qt * 64 + wrow + (lane >> 2);
    const int grow1 = grow0 + 8;

    for (int jb = 0; jb < nblk; jb++) {
        const int st = jb & 1;
        if (jb + 1 < nblk) {
            asm volatile("cp.async.wait_group 1;" ::: "memory");
        } else {
            asm volatile("cp.async.wait_group 0;" ::: "memory");
        }
        __syncthreads();

        const uint32_t kvb = oKV + st * stKV;

        // ---- S = Q K^T : per-warp 16x32 frags
        float sa[4][4];
#pragma unroll
        for (int nt = 0; nt < 4; nt++)
#pragma unroll
            for (int j = 0; j < 4; j++) sa[nt][j] = 0.f;

#pragma unroll
        for (int kt = 0; kt < 8; kt++) {
            const int kc = kt << 4;
            uint32_t ah[4], al[4];
            {
                int r = wrow + (lane & 15);
                int cc = kc + ((lane >> 4) << 3);
                LDSM4(ah[0], ah[1], ah[2], ah[3], usm + (uint32_t)(oQH + r * QLD + cc) * 2);
                LDSM4(al[0], al[1], al[2], al[3], usm + (uint32_t)(oQL + r * QLD + cc) * 2);
            }
#pragma unroll
            for (int ntp = 0; ntp < 2; ntp++) {
                int r = (ntp << 4) + (lane & 7) + (((lane >> 4) & 1) << 3);
                int cc = kc + (((lane >> 3) & 1) << 3);
                uint32_t bhh[4], bll[4];
                LDSM4(bhh[0], bhh[1], bhh[2], bhh[3], usm + (kvb + r * QLD + cc) * 2);
                LDSM4(bll[0], bll[1], bll[2], bll[3], usm + (kvb + 4352 + r * QLD + cc) * 2);
#pragma unroll
                for (int t = 0; t < 2; t++) {
                    int nt = (ntp << 1) + t;
                    MMA16816(sa[nt], ah, bhh[2*t], bhh[2*t+1]);
                    MMA16816(sa[nt], ah, bll[2*t], bll[2*t+1]);
                    MMA16816(sa[nt], al, bhh[2*t], bhh[2*t+1]);
                }
            }
        }

        // ---- scale (+mask)
        const bool needmask = (jb >= 2 * qt);
#pragma unroll
        for (int nt = 0; nt < 4; nt++) {
            int cb = jb * 32 + (nt << 3) + ((lane & 3) << 1);
#pragma unroll
            for (int j = 0; j < 4; j++) {
                float x = sa[nt][j] * SCL2;
                if (needmask) {
                    int col = cb + (j & 1);
                    int row = (j < 2) ? grow0 : grow1;
                    if (col > row) x = -1e30f;
                }
                sa[nt][j] = x;
            }
        }

        // ---- online softmax
        float rm0 = -1e30f, rm1 = -1e30f;
#pragma unroll
        for (int nt = 0; nt < 4; nt++) {
            rm0 = fmaxf(rm0, fmaxf(sa[nt][0], sa[nt][1]));
            rm1 = fmaxf(rm1, fmaxf(sa[nt][2], sa[nt][3]));
        }
        rm0 = fmaxf(rm0, __shfl_xor_sync(0xffffffffu, rm0, 1));
        rm0 = fmaxf(rm0, __shfl_xor_sync(0xffffffffu, rm0, 2));
        rm1 = fmaxf(rm1, __shfl_xor_sync(0xffffffffu, rm1, 1));
        rm1 = fmaxf(rm1, __shfl_xor_sync(0xffffffffu, rm1, 2));
        float mn0 = fmaxf(m0r, rm0), mn1 = fmaxf(m1r, rm1);
        float al0 = exp2f(m0r - mn0), al1 = exp2f(m1r - mn1);
        m0r = mn0; m1r = mn1;

        float rs0 = 0.f, rs1 = 0.f;
#pragma unroll
        for (int nt = 0; nt < 4; nt++) {
            float p0 = exp2f(sa[nt][0] - mn0);
            float p1 = exp2f(sa[nt][1] - mn0);
            float p2 = exp2f(sa[nt][2] - mn1);
            float p3 = exp2f(sa[nt][3] - mn1);
            sa[nt][0] = p0; sa[nt][1] = p1; sa[nt][2] = p2; sa[nt][3] = p3;
            rs0 += p0 + p1; rs1 += p2 + p3;
        }
        rs0 += __shfl_xor_sync(0xffffffffu, rs0, 1);
        rs0 += __shfl_xor_sync(0xffffffffu, rs0, 2);
        rs1 += __shfl_xor_sync(0xffffffffu, rs1, 1);
        rs1 += __shfl_xor_sync(0xffffffffu, rs1, 2);
        l0r = l0r * al0 + rs0;
        l1r = l1r * al1 + rs1;

#pragma unroll
        for (int nt = 0; nt < 16; nt++) {
            oa[nt][0] *= al0; oa[nt][1] *= al0;
            oa[nt][2] *= al1; oa[nt][3] *= al1;
        }

        // ---- O += P V  (P 16x32 -> 2 A-frag chunks; V [d][s] tiles)
#pragma unroll
        for (int kt2 = 0; kt2 < 2; kt2++) {
            const int t0 = kt2 << 1, t1 = t0 + 1;
            uint32_t pah[4], pal[4];
            {
                __nv_bfloat162 hh, ll;
                float p0, p1, r0, r1;
                p0 = sa[t0][0]; p1 = sa[t0][1];
                hh = __floats2bfloat162_rn(p0, p1);
                r0 = p0 - __bfloat162float(hh.x); r1 = p1 - __bfloat162float(hh.y);
                ll = __floats2bfloat162_rn(r0, r1);
                pah[0] = *(uint32_t*)&hh; pal[0] = *(uint32_t*)&ll;
                p0 = sa[t0][2]; p1 = sa[t0][3];
                hh = __floats2bfloat162_rn(p0, p1);
                r0 = p0 - __bfloat162float(hh.x); r1 = p1 - __bfloat162float(hh.y);
                ll = __floats2bfloat162_rn(r0, r1);
                pah[1] = *(uint32_t*)&hh; pal[1] = *(uint32_t*)&ll;
                p0 = sa[t1][0]; p1 = sa[t1][1];
                hh = __floats2bfloat162_rn(p0, p1);
                r0 = p0 - __bfloat162float(hh.x); r1 = p1 - __bfloat162float(hh.y);
                ll = __floats2bfloat162_rn(r0, r1);
                pah[2] = *(uint32_t*)&hh; pal[2] = *(uint32_t*)&ll;
                p0 = sa[t1][2]; p1 = sa[t1][3];
                hh = __floats2bfloat162_rn(p0, p1);
                r0 = p0 - __bfloat162float(hh.x); r1 = p1 - __bfloat162float(hh.y);
                ll = __floats2bfloat162_rn(r0, r1);
                pah[3] = *(uint32_t*)&hh; pal[3] = *(uint32_t*)&ll;
            }
            const int cv = (kt2 << 4) + (((lane >> 3) & 1) << 3);
#pragma unroll
            for (int ntp = 0; ntp < 8; ntp++) {
                int r = (ntp << 4) + (lane & 7) + (((lane >> 4) & 1) << 3);
                uint32_t vhh[4], vll[4];
                LDSM4(vhh[0], vhh[1], vhh[2], vhh[3], usm + (kvb + 8704 + r * VLD + cv) * 2);
                LDSM4(vll[0], vll[1], vll[2], vll[3], usm + (kvb + 13824 + r * VLD + cv) * 2);
#pragma unroll
                for (int t = 0; t < 2; t++) {
                    int nt = (ntp << 1) + t;
                    MMA16816(oa[nt], pah, vhh[2*t], vhh[2*t+1]);
                    MMA16816(oa[nt], pah, vll[2*t], vll[2*t+1]);
                    MMA16816(oa[nt], pal, vhh[2*t], vhh[2*t+1]);
                }
            }
        }

        __syncthreads();
        if (jb + 2 < nblk) LOAD_KV(st, jb + 2);
    }

    // ---- epilogue: O /= l, hi/lo split into acat [m][4096]
    float inv0 = 1.f / l0r, inv1 = 1.f / l1r;
    int srow0 = qt * 64 + wrow + (lane >> 2);
    int mrow0 = b * S_ + srow0;
    __nv_bfloat16* a0 = acat + (size_t)mrow0 * K2_ + (h << 7);
    __nv_bfloat16* a1 = a0 + (size_t)8 * K2_;
#pragma unroll
    for (int nt = 0; nt < 16; nt++) {
        int cb = (nt << 3) + ((lane & 3) << 1);
        float v00 = oa[nt][0] * inv0, v01 = oa[nt][1] * inv0;
        float v10 = oa[nt][2] * inv1, v11 = oa[nt][3] * inv1;
        __nv_bfloat162 h0 = __floats2bfloat162_rn(v00, v01);
        __nv_bfloat162 l0p = __floats2bfloat162_rn(v00 - __bfloat162float(h0.x),
                                                   v01 - __bfloat162float(h0.y));
        __nv_bfloat162 h1 = __floats2bfloat162_rn(v10, v11);
        __nv_bfloat162 l1p = __floats2bfloat162_rn(v10 - __bfloat162float(h1.x),
                                                   v11 - __bfloat162float(h1.y));
        *(__nv_bfloat162*)(a0 + cb)        = h0;
        *(__nv_bfloat162*)(a0 + 2048 + cb) = l0p;
        *(__nv_bfloat162*)(a1 + cb)        = h1;
        *(__nv_bfloat162*)(a1 + 2048 + cb) = l1p;
    }
}

// ---------------- launch ----------------
extern "C" void kernel_launch(void* const* d_in, const int* in_sizes, int n_in,
                              void* d_out, int out_size)
{
    const float* query = (const float*)d_in[0];
    const float* key   = (const float*)d_in[1];
    const float* value = (const float*)d_in[2];
    const float* wq = (const float*)d_in[4];
    const float* bq = (const float*)d_in[5];
    const float* wk = (const float*)d_in[6];
    const float* bk = (const float*)d_in[7];
    const float* wv = (const float*)d_in[8];
    const float* bv = (const float*)d_in[9];
    const float* wo = (const float*)d_in[10];
    const float* bo = (const float*)d_in[11];
    float* out = (float*)d_out;

    __nv_bfloat16 *ac0, *ac1, *ac2, *wc0, *wc1, *wc2, *wc3;
    __nv_bfloat16 *qh, *ql, *kh, *kl, *vth, *vtl;
    cudaGetSymbolAddress((void**)&ac0, g_acat0);
    cudaGetSymbolAddress((void**)&ac1, g_acat1);
    cudaGetSymbolAddress((void**)&ac2, g_acat2);
    cudaGetSymbolAddress((void**)&wc0, g_wcat0);
    cudaGetSymbolAddress((void**)&wc1, g_wcat1);
    cudaGetSymbolAddress((void**)&wc2, g_wcat2);
    cudaGetSymbolAddress((void**)&wc3, g_wcat3);
    cudaGetSymbolAddress((void**)&qh, g_qh);
    cudaGetSymbolAddress((void**)&ql, g_ql);
    cudaGetSymbolAddress((void**)&kh, g_kh);
    cudaGetSymbolAddress((void**)&kl, g_kl);
    cudaGetSymbolAddress((void**)&vth, g_vth);
    cudaGetSymbolAddress((void**)&vtl, g_vtl);

    cudaFuncSetAttribute(gemm_qkv, cudaFuncAttributeMaxDynamicSharedMemorySize, GEMM_SMEM);
    cudaFuncSetAttribute(gemm_out, cudaFuncAttributeMaxDynamicSharedMemorySize, GEMM_SMEM);
    cudaFuncSetAttribute(attn_mma, cudaFuncAttributeMaxDynamicSharedMemorySize, ATTN2_SMEM);

    rope_table<<<(S_ * 64) / 256, 256>>>();

    split_all<<<40960, 256>>>(query, key, value, wq, wk, wv, wo,
                              ac0, ac1, ac2, wc0, wc1, wc2, wc3);

    gemm_qkv<<<dim3(D_/128, M_/128, 3), 256, GEMM_SMEM>>>(
        ac0, ac1, ac2, wc0, wc1, wc2, bq, bk, bv, qh, ql, kh, kl, vth, vtl);

    attn_mma<<<dim3(S_ / 64, BH_), 128, ATTN2_SMEM>>>(qh, ql, kh, kl, vth, vtl, ac0);

    gemm_out<<<dim3(D_/128, M_/128), 256, GEMM_SMEM>>>(ac0, wc3, bo, out);
}

// round 13
// speedup vs baseline: 1.4234x; 1.4234x over previous
#include <cuda_runtime.h>
#include <cuda_fp16.h>
#include <math.h>
#include <stdint.h>

#define B_  2
#define S_  2048
#define D_  2048
#define H_  16
#define DK_ 128
#define M_  (B_*S_)   // 4096
#define BH_ (B_*H_)   // 32
#define K2_ 4096      // activations: [hi | lo] fp16
#define KW_ 2048      // weights: single fp16

// ---------------- scratch (device globals; no allocs allowed) ----------------
__device__ __half g_acat0[M_*K2_];  // query split / attn-out split
__device__ __half g_acat1[M_*K2_];  // key split
__device__ __half g_acat2[M_*K2_];  // value split
__device__ __half g_wcat0[D_*KW_];  // wq (single)
__device__ __half g_wcat1[D_*KW_];  // wk
__device__ __half g_wcat2[D_*KW_];  // wv
__device__ __half g_wcat3[D_*KW_];  // wo
__device__ float g_cos[S_*64];
__device__ float g_sin[S_*64];
__device__ __half g_qh[BH_*S_*DK_], g_ql[BH_*S_*DK_];  // q split
__device__ __half g_kh[BH_*S_*DK_];                    // k single
__device__ __half g_vth[BH_*DK_*S_];                   // v single, [bh][d][s]

__device__ __forceinline__ uint32_t smem_u32(const void* p) {
    uint32_t a;
    asm("{ .reg .u64 t; cvta.to.shared.u64 t, %1; cvt.u32.u64 %0, t; }" : "=r"(a) : "l"(p));
    return a;
}

#define LDSM4(r0,r1,r2,r3, addr) \
    asm volatile("ldmatrix.sync.aligned.m8n8.x4.shared.b16 {%0,%1,%2,%3}, [%4];" \
        : "=r"(r0), "=r"(r1), "=r"(r2), "=r"(r3) : "r"(addr))

#define MMA16816(d, a, b0v, b1v) \
    asm volatile("mma.sync.aligned.m16n8k16.row.col.f32.f16.f16.f32 " \
        "{%0,%1,%2,%3}, {%4,%5,%6,%7}, {%8,%9}, {%0,%1,%2,%3};" \
        : "+f"((d)[0]), "+f"((d)[1]), "+f"((d)[2]), "+f"((d)[3]) \
        : "r"((a)[0]), "r"((a)[1]), "r"((a)[2]), "r"((a)[3]), "r"(b0v), "r"(b1v))

#define CPA16(dst, src) \
    asm volatile("cp.async.cg.shared.global [%0], [%1], 16;" :: "r"(dst), "l"(src))

// ---------------- splits: activations hi/lo, weights single ----------------
__device__ __forceinline__ void split_act(
    const float* __restrict__ x, __half* __restrict__ out, int lb)
{
    int i4 = (lb * 256 + threadIdx.x) * 4;
    int r = i4 >> 11, c = i4 & 2047;
    float4 v = *(const float4*)(x + i4);
    __half2 H01 = __floats2half2_rn(v.x, v.y);
    __half2 H23 = __floats2half2_rn(v.z, v.w);
    __half2 L01 = __floats2half2_rn(v.x - __half2float(__low2half(H01)),
                                    v.y - __half2float(__high2half(H01)));
    __half2 L23 = __floats2half2_rn(v.z - __half2float(__low2half(H23)),
                                    v.w - __half2float(__high2half(H23)));
    __half* row = out + (size_t)r * K2_ + c;
    *(__half2*)(row)            = H01;
    *(__half2*)(row + 2)        = H23;
    *(__half2*)(row + 2048)     = L01;
    *(__half2*)(row + 2048 + 2) = L23;
}

__device__ __forceinline__ void split_w(
    const float* __restrict__ x, __half* __restrict__ out, int lb)
{
    int i4 = (lb * 256 + threadIdx.x) * 4;
    float4 v = *(const float4*)(x + i4);
    *(__half2*)(out + i4)     = __floats2half2_rn(v.x, v.y);
    *(__half2*)(out + i4 + 2) = __floats2half2_rn(v.z, v.w);
}

// blocks: 3x8192 activations, then 4x4096 weights
__global__ __launch_bounds__(256) void split_all(
    const float* q, const float* k, const float* v,
    const float* wq, const float* wk, const float* wv, const float* wo,
    __half* a0, __half* a1, __half* a2,
    __half* w0, __half* w1, __half* w2, __half* w3)
{
    int bx = blockIdx.x;
    if (bx < 8192)        split_act(q, a0, bx);
    else if (bx < 16384)  split_act(k, a1, bx - 8192);
    else if (bx < 24576)  split_act(v, a2, bx - 16384);
    else {
        int t = bx - 24576, z = t >> 12, lb = t & 4095;
        const float* x = z == 0 ? wq : (z == 1 ? wk : (z == 2 ? wv : wo));
        __half* o = z == 0 ? w0 : (z == 1 ? w1 : (z == 2 ? w2 : w3));
        split_w(x, o, lb);
    }
}

// ---------------- RoPE table ----------------
__global__ __launch_bounds__(256) void rope_table()
{
    int idx = blockIdx.x * blockDim.x + threadIdx.x;
    if (idx >= S_ * 64) return;
    int i = idx & 63;
    int s = idx >> 6;
    float inv = powf(10000.f, -(float)(2 * i) / 128.f);
    float ph  = (float)s * inv;
    g_cos[idx] = cosf(ph);
    g_sin[idx] = sinf(ph);
}

// ---------------- 2-term fp16 GEMM: C = (Ahi+Alo) * W^T + bias ----------------
// 128x128 tile, 8 warps (2x4), 32-col chunks, 3-stage ring, XOR swizzle.
// modes: 0 fp32 out; 1 rope+split(q); 2 transpose single(v); 3 rope single(k)
#define BUF_B 8192
#define STAGE_B (3*BUF_B)             // Ahi, Alo, W = 24576 B
#define NSTG 3
#define GEMM_SMEM (NSTG*STAGE_B)      // 73728 B
#define NCH2 64
#define SWX(r, cI) ((uint32_t)((r)*64 + ((((cI) ^ (((r)>>1)&3)) & 3) << 4)))
#define LDE 133

__device__ __forceinline__ void gemm_body(
    const __half* __restrict__ A, const __half* __restrict__ Wt,
    const float* __restrict__ bias, int mode, float* __restrict__ C,
    __half* __restrict__ bho, __half* __restrict__ blo)
{
    extern __shared__ __half sm[];
    const int tid = threadIdx.x;
    const int lane = tid & 31, w = tid >> 5;
    const int wm = (w >> 2) << 6;
    const int wn = (w & 3) << 5;
    const int m0 = blockIdx.y << 7, n0 = blockIdx.x << 7;

    const __half* Ag = A  + (size_t)m0 * K2_;
    const __half* Wg = Wt + (size_t)n0 * KW_;

    float acc[4][4][4];
#pragma unroll
    for (int mi = 0; mi < 4; mi++)
#pragma unroll
        for (int ni = 0; ni < 4; ni++)
#pragma unroll
            for (int j = 0; j < 4; j++) acc[mi][ni][j] = 0.f;

    const int r0 = tid >> 2,        cI0 = tid & 3;
    const int r1 = (tid >> 2) + 64, cI1 = tid & 3;
    const uint32_t so0 = SWX(r0, cI0), so1 = SWX(r1, cI1);
    const int e0 = cI0 << 3, e1 = cI1 << 3;
#define LOAD_CHUNK2(stage, chunk) do {                                           \
    uint32_t sb = smem_u32((const char*)sm + (stage) * STAGE_B);                 \
    const size_t off = (size_t)(chunk) * 32;                                     \
    CPA16(sb + so0,            Ag + (size_t)r0*K2_ + off + e0);                  \
    CPA16(sb + so1,            Ag + (size_t)r1*K2_ + off + e1);                  \
    CPA16(sb + BUF_B + so0,    Ag + (size_t)r0*K2_ + 2048 + off + e0);           \
    CPA16(sb + BUF_B + so1,    Ag + (size_t)r1*K2_ + 2048 + off + e1);           \
    CPA16(sb + 2*BUF_B + so0,  Wg + (size_t)r0*KW_ + off + e0);                  \
    CPA16(sb + 2*BUF_B + so1,  Wg + (size_t)r1*KW_ + off + e1);                  \
    asm volatile("cp.async.commit_group;" ::: "memory");                         \
} while (0)

    LOAD_CHUNK2(0, 0);
    LOAD_CHUNK2(1, 1);

    for (int c = 0; c < NCH2; c++) {
        const int s = c % NSTG;
        if (c + 1 < NCH2) {
            asm volatile("cp.async.wait_group 1;" ::: "memory");
        } else {
            asm volatile("cp.async.wait_group 0;" ::: "memory");
        }
        __syncthreads();

        if (c + 2 < NCH2) LOAD_CHUNK2((c + 2) % NSTG, c + 2);

        const uint32_t sb = smem_u32((const char*)sm + s * STAGE_B);
#pragma unroll
        for (int ks = 0; ks < 2; ks++) {
            const int kbase = ks << 1;
            uint32_t ah[4][4], al[4][4];
#pragma unroll
            for (int mi = 0; mi < 4; mi++) {
                int r = wm + (mi << 4) + (lane & 15);
                int cI = kbase + (lane >> 4);
                uint32_t off = SWX(r, cI);
                LDSM4(ah[mi][0], ah[mi][1], ah[mi][2], ah[mi][3], sb + off);
                LDSM4(al[mi][0], al[mi][1], al[mi][2], al[mi][3], sb + BUF_B + off);
            }
            uint32_t bw[4][2];
#pragma unroll
            for (int nb = 0; nb < 2; nb++) {
                int r = wn + (nb << 4) + (lane & 7) + (((lane >> 4) & 1) << 3);
                int cI = kbase + ((lane >> 3) & 1);
                uint32_t off = SWX(r, cI);
                LDSM4(bw[nb*2][0], bw[nb*2][1], bw[nb*2+1][0], bw[nb*2+1][1],
                      sb + 2*BUF_B + off);
            }
#pragma unroll
            for (int mi = 0; mi < 4; mi++)
#pragma unroll
                for (int ni = 0; ni < 4; ni++) {
                    MMA16816(acc[mi][ni], ah[mi], bw[ni][0], bw[ni][1]);
                    MMA16816(acc[mi][ni], al[mi], bw[ni][0], bw[ni][1]);
                }
        }
    }

    if (mode == 0) {
#pragma unroll
        for (int mi = 0; mi < 4; mi++) {
#pragma unroll
            for (int half = 0; half < 2; half++) {
                int m = m0 + wm + (mi << 4) + (lane >> 2) + (half << 3);
#pragma unroll
                for (int ni = 0; ni < 4; ni++) {
                    int n = n0 + wn + (ni << 3) + ((lane & 3) << 1);
                    float2 o;
                    o.x = acc[mi][ni][half*2+0] + bias[n];
                    o.y = acc[mi][ni][half*2+1] + bias[n+1];
                    *(float2*)(C + (size_t)m * D_ + n) = o;
                }
            }
        }
        return;
    }

    // staged fp32 tile in smem, then fused epilogue
    __syncthreads();
    float* sf = (float*)sm;
#pragma unroll
    for (int mi = 0; mi < 4; mi++)
#pragma unroll
        for (int half = 0; half < 2; half++) {
            int ml = wm + (mi << 4) + (lane >> 2) + (half << 3);
#pragma unroll
            for (int ni = 0; ni < 4; ni++) {
                int nl = wn + (ni << 3) + ((lane & 3) << 1);
                sf[ml*LDE + nl]     = acc[mi][ni][half*2+0] + bias[n0 + nl];
                sf[ml*LDE + nl + 1] = acc[mi][ni][half*2+1] + bias[n0 + nl + 1];
            }
        }
    __syncthreads();

    const int b  = m0 >> 11;
    const int s0 = m0 & (S_ - 1);
    const int h  = n0 >> 7;
    const int bh = b * H_ + h;

    if (mode == 1 || mode == 3) {
        for (int idx = tid; idx < 128 * 64; idx += 256) {
            int r = idx >> 6, i = idx & 63;
            int s = s0 + r;
            float x1 = sf[r*LDE + i], x2 = sf[r*LDE + 64 + i];
            float cc = g_cos[(s << 6) + i], sn = g_sin[(s << 6) + i];
            float v1 = x1 * cc - x2 * sn;
            float v2 = x2 * cc + x1 * sn;
            size_t o = (((size_t)bh * S_ + s) << 7) + i;
            __half h1 = __float2half_rn(v1);
            __half h2 = __float2half_rn(v2);
            bho[o]      = h1;
            bho[o + 64] = h2;
            if (mode == 1) {
                blo[o]      = __float2half_rn(v1 - __half2float(h1));
                blo[o + 64] = __float2half_rn(v2 - __half2float(h2));
            }
        }
    } else {
        // mode 2: transpose, single fp16 -> [bh][d][s]
        for (int idx = tid; idx < 128 * 128; idx += 256) {
            int d = idx >> 7, sl = idx & 127;
            bho[((size_t)bh * DK_ + d) * S_ + s0 + sl] = __float2half_rn(sf[sl*LDE + d]);
        }
    }
}

__global__ __launch_bounds__(256, 2) void gemm_qkv(
    const __half* a0, const __half* a1, const __half* a2,
    const __half* w0, const __half* w1, const __half* w2,
    const float* b0, const float* b1, const float* b2,
    __half* qh, __half* ql, __half* kh, __half* vth)
{
    int z = blockIdx.z;
    const __half* A = z == 0 ? a0 : (z == 1 ? a1 : a2);
    const __half* W = z == 0 ? w0 : (z == 1 ? w1 : w2);
    const float* bias = z == 0 ? b0 : (z == 1 ? b1 : b2);
    if (z == 0)      gemm_body(A, W, bias, 1, (float*)0, qh, ql);
    else if (z == 1) gemm_body(A, W, bias, 3, (float*)0, kh, (__half*)0);
    else             gemm_body(A, W, bias, 2, (float*)0, vth, (__half*)0);
}

__global__ __launch_bounds__(256, 2) void gemm_out(
    const __half* A, const __half* W, const float* bias, float* C)
{
    gemm_body(A, W, bias, 0, C, (__half*)0, (__half*)0);
}

// ---------------- fp16 tensor-core causal flash attention ----------------
// BR=128 (8 warps x 16 rows, 256 thr), BC=64, 2-stage KV.
// Q split (hi/lo), K single, V single. S: 2 MMA terms; PV: 2 terms (p split).
#define QLD 136
#define VLD 72
#define oQH 0
#define oQL 17408
#define oKV 34816
#define stKV 17920          // K 64x136=8704 elems + V 128x72=9216 elems
#define ATTN2_SMEM ((oKV + 2*stKV)*2)   // 141312 B

__global__ __launch_bounds__(256, 1) void attn_mma(
    const __half* __restrict__ gqh, const __half* __restrict__ gql,
    const __half* __restrict__ gkh, const __half* __restrict__ gvh,
    __half* __restrict__ acat)
{
    extern __shared__ __half smb[];
    const uint32_t usm = smem_u32(smb);
    const int tid = threadIdx.x;
    const int lane = tid & 31, w = tid >> 5;
    const int wrow = w << 4;
    const int qt = gridDim.x - 1 - blockIdx.x;
    const int bh = blockIdx.y;
    const int b  = bh >> 4, h = bh & 15;
    const int nblk = 2 * qt + 2;
    const float SCL2 = 0.12751743f;     // 1/sqrt(128) * log2(e)

    const size_t qbase = ((size_t)bh * S_ + (size_t)qt * 128) << 7;

    {
#pragma unroll
        for (int i = 0; i < 8; i++) {
            int ch = tid + (i << 8);
            int r = ch >> 4, c8 = (ch & 15) << 3;
            CPA16(usm + (uint32_t)(oQH + r * QLD + c8) * 2, gqh + qbase + ((size_t)r << 7) + c8);
            CPA16(usm + (uint32_t)(oQL + r * QLD + c8) * 2, gql + qbase + ((size_t)r << 7) + c8);
        }
    }
#define LOAD_KV(stage, jb) do {                                                      \
    uint32_t kvb = oKV + (stage) * stKV;                                             \
    size_t kbase = ((size_t)bh * S_ + (size_t)(jb) * 64) << 7;                       \
    _Pragma("unroll")                                                                \
    for (int i = 0; i < 4; i++) {                                                    \
        int ch = tid + (i << 8);                                                     \
        int r = ch >> 4, c8 = (ch & 15) << 3;                                        \
        CPA16(usm + (kvb + r * QLD + c8) * 2, gkh + kbase + ((size_t)r << 7) + c8);  \
    }                                                                                \
    size_t vbase = ((size_t)bh * DK_) * S_ + (size_t)(jb) * 64;                      \
    _Pragma("unroll")                                                                \
    for (int i = 0; i < 4; i++) {                                                    \
        int ch = tid + (i << 8);                                                     \
        int r = ch >> 3, c8 = (ch & 7) << 3;                                         \
        CPA16(usm + (kvb + 8704 + r * VLD + c8) * 2, gvh + vbase + (size_t)r * S_ + c8); \
    }                                                                                \
    asm volatile("cp.async.commit_group;" ::: "memory");                             \
} while (0)

    LOAD_KV(0, 0);
    LOAD_KV(1, 1);

    float oa[16][4];
#pragma unroll
    for (int nt = 0; nt < 16; nt++)
#pragma unroll
        for (int j = 0; j < 4; j++) oa[nt][j] = 0.f;
    float m0r = -1e30f, m1r = -1e30f, l0r = 0.f, l1r = 0.f;

    const int grow0 = qt * 128 + wrow + (lane >> 2);
    const int grow1 = grow0 + 8;

    for (int jb = 0; jb < nblk; jb++) {
        const int st = jb & 1;
        if (jb + 1 < nblk) {
            asm volatile("cp.async.wait_group 1;" ::: "memory");
        } else {
            asm volatile("cp.async.wait_group 0;" ::: "memory");
        }
        __syncthreads();

        const uint32_t kvb = oKV + st * stKV;

        // ---- S = Q K^T : q-split x k-single, per-warp 16x64
        float sa[8][4];
#pragma unroll
        for (int nt = 0; nt < 8; nt++)
#pragma unroll
            for (int j = 0; j < 4; j++) sa[nt][j] = 0.f;

#pragma unroll
        for (int kt = 0; kt < 8; kt++) {
            const int kc = kt << 4;
            uint32_t ah[4], al[4];
            {
                int r = wrow + (lane & 15);
                int cc = kc + ((lane >> 4) << 3);
                LDSM4(ah[0], ah[1], ah[2], ah[3], usm + (uint32_t)(oQH + r * QLD + cc) * 2);
                LDSM4(al[0], al[1], al[2], al[3], usm + (uint32_t)(oQL + r * QLD + cc) * 2);
            }
#pragma unroll
            for (int ntp = 0; ntp < 4; ntp++) {
                int r = (ntp << 4) + (lane & 7) + (((lane >> 4) & 1) << 3);
                int cc = kc + (((lane >> 3) & 1) << 3);
                uint32_t bk[4];
                LDSM4(bk[0], bk[1], bk[2], bk[3], usm + (kvb + r * QLD + cc) * 2);
#pragma unroll
                for (int t = 0; t < 2; t++) {
                    int nt = (ntp << 1) + t;
                    MMA16816(sa[nt], ah, bk[2*t], bk[2*t+1]);
                    MMA16816(sa[nt], al, bk[2*t], bk[2*t+1]);
                }
            }
        }

        const bool needmask = (jb >= 2 * qt);
#pragma unroll
        for (int nt = 0; nt < 8; nt++) {
            int cb = jb * 64 + (nt << 3) + ((lane & 3) << 1);
#pragma unroll
            for (int j = 0; j < 4; j++) {
                float x = sa[nt][j] * SCL2;
                if (needmask) {
                    int col = cb + (j & 1);
                    int row = (j < 2) ? grow0 : grow1;
                    if (col > row) x = -1e30f;
                }
                sa[nt][j] = x;
            }
        }

        float rm0 = -1e30f, rm1 = -1e30f;
#pragma unroll
        for (int nt = 0; nt < 8; nt++) {
            rm0 = fmaxf(rm0, fmaxf(sa[nt][0], sa[nt][1]));
            rm1 = fmaxf(rm1, fmaxf(sa[nt][2], sa[nt][3]));
        }
        rm0 = fmaxf(rm0, __shfl_xor_sync(0xffffffffu, rm0, 1));
        rm0 = fmaxf(rm0, __shfl_xor_sync(0xffffffffu, rm0, 2));
        rm1 = fmaxf(rm1, __shfl_xor_sync(0xffffffffu, rm1, 1));
        rm1 = fmaxf(rm1, __shfl_xor_sync(0xffffffffu, rm1, 2));
        float mn0 = fmaxf(m0r, rm0), mn1 = fmaxf(m1r, rm1);
        float al0 = exp2f(m0r - mn0), al1 = exp2f(m1r - mn1);
        m0r = mn0; m1r = mn1;

        float rs0 = 0.f, rs1 = 0.f;
#pragma unroll
        for (int nt = 0; nt < 8; nt++) {
            float p0 = exp2f(sa[nt][0] - mn0);
            float p1 = exp2f(sa[nt][1] - mn0);
            float p2 = exp2f(sa[nt][2] - mn1);
            float p3 = exp2f(sa[nt][3] - mn1);
            sa[nt][0] = p0; sa[nt][1] = p1; sa[nt][2] = p2; sa[nt][3] = p3;
            rs0 += p0 + p1; rs1 += p2 + p3;
        }
        rs0 += __shfl_xor_sync(0xffffffffu, rs0, 1);
        rs0 += __shfl_xor_sync(0xffffffffu, rs0, 2);
        rs1 += __shfl_xor_sync(0xffffffffu, rs1, 1);
        rs1 += __shfl_xor_sync(0xffffffffu, rs1, 2);
        l0r = l0r * al0 + rs0;
        l1r = l1r * al1 + rs1;

#pragma unroll
        for (int nt = 0; nt < 16; nt++) {
            oa[nt][0] *= al0; oa[nt][1] *= al0;
            oa[nt][2] *= al1; oa[nt][3] *= al1;
        }

        // ---- O += P V : p-split x v-single
#pragma unroll
        for (int kt2 = 0; kt2 < 4; kt2++) {
            const int t0 = kt2 << 1, t1 = t0 + 1;
            uint32_t pah[4], pal[4];
            {
                __half2 hh, ll;
                float p0, p1, r0, r1;
                p0 = sa[t0][0]; p1 = sa[t0][1];
                hh = __floats2half2_rn(p0, p1);
                r0 = p0 - __half2float(__low2half(hh)); r1 = p1 - __half2float(__high2half(hh));
                ll = __floats2half2_rn(r0, r1);
                pah[0] = *(uint32_t*)&hh; pal[0] = *(uint32_t*)&ll;
                p0 = sa[t0][2]; p1 = sa[t0][3];
                hh = __floats2half2_rn(p0, p1);
                r0 = p0 - __half2float(__low2half(hh)); r1 = p1 - __half2float(__high2half(hh));
                ll = __floats2half2_rn(r0, r1);
                pah[1] = *(uint32_t*)&hh; pal[1] = *(uint32_t*)&ll;
                p0 = sa[t1][0]; p1 = sa[t1][1];
                hh = __floats2half2_rn(p0, p1);
                r0 = p0 - __half2float(__low2half(hh)); r1 = p1 - __half2float(__high2half(hh));
                ll = __floats2half2_rn(r0, r1);
                pah[2] = *(uint32_t*)&hh; pal[2] = *(uint32_t*)&ll;
                p0 = sa[t1][2]; p1 = sa[t1][3];
                hh = __floats2half2_rn(p0, p1);
                r0 = p0 - __half2float(__low2half(hh)); r1 = p1 - __half2float(__high2half(hh));
                ll = __floats2half2_rn(r0, r1);
                pah[3] = *(uint32_t*)&hh; pal[3] = *(uint32_t*)&ll;
            }
            const int cv = (kt2 << 4) + (((lane >> 3) & 1) << 3);
#pragma unroll
            for (int ntp = 0; ntp < 8; ntp++) {
                int r = (ntp << 4) + (lane & 7) + (((lane >> 4) & 1) << 3);
                uint32_t vv[4];
                LDSM4(vv[0], vv[1], vv[2], vv[3], usm + (kvb + 8704 + r * VLD + cv) * 2);
#pragma unroll
                for (int t = 0; t < 2; t++) {
                    int nt = (ntp << 1) + t;
                    MMA16816(oa[nt], pah, vv[2*t], vv[2*t+1]);
                    MMA16816(oa[nt], pal, vv[2*t], vv[2*t+1]);
                }
            }
        }

        __syncthreads();
        if (jb + 2 < nblk) LOAD_KV(st, jb + 2);
    }

    // ---- epilogue: O /= l, hi/lo fp16 split into acat [m][4096]
    float inv0 = 1.f / l0r, inv1 = 1.f / l1r;
    int srow0 = qt * 128 + wrow + (lane >> 2);
    int mrow0 = b * S_ + srow0;
    __half* a0 = acat + (size_t)mrow0 * K2_ + (h << 7);
    __half* a1 = a0 + (size_t)8 * K2_;
#pragma unroll
    for (int nt = 0; nt < 16; nt++) {
        int cb = (nt << 3) + ((lane & 3) << 1);
        float v00 = oa[nt][0] * inv0, v01 = oa[nt][1] * inv0;
        float v10 = oa[nt][2] * inv1, v11 = oa[nt][3] * inv1;
        __half2 h0 = __floats2half2_rn(v00, v01);
        __half2 l0p = __floats2half2_rn(v00 - __half2float(__low2half(h0)),
                                        v01 - __half2float(__high2half(h0)));
        __half2 h1 = __floats2half2_rn(v10, v11);
        __half2 l1p = __floats2half2_rn(v10 - __half2float(__low2half(h1)),
                                        v11 - __half2float(__high2half(h1)));
        *(__half2*)(a0 + cb)        = h0;
        *(__half2*)(a0 + 2048 + cb) = l0p;
        *(__half2*)(a1 + cb)        = h1;
        *(__half2*)(a1 + 2048 + cb) = l1p;
    }
}

// ---------------- launch ----------------
extern "C" void kernel_launch(void* const* d_in, const int* in_sizes, int n_in,
                              void* d_out, int out_size)
{
    const float* query = (const float*)d_in[0];
    const float* key   = (const float*)d_in[1];
    const float* value = (const float*)d_in[2];
    const float* wq = (const float*)d_in[4];
    const float* bq = (const float*)d_in[5];
    const float* wk = (const float*)d_in[6];
    const float* bk = (const float*)d_in[7];
    const float* wv = (const float*)d_in[8];
    const float* bv = (const float*)d_in[9];
    const float* wo = (const float*)d_in[10];
    const float* bo = (const float*)d_in[11];
    float* out = (float*)d_out;

    __half *ac0, *ac1, *ac2, *wc0, *wc1, *wc2, *wc3;
    __half *qh, *ql, *kh, *vth;
    cudaGetSymbolAddress((void**)&ac0, g_acat0);
    cudaGetSymbolAddress((void**)&ac1, g_acat1);
    cudaGetSymbolAddress((void**)&ac2, g_acat2);
    cudaGetSymbolAddress((void**)&wc0, g_wcat0);
    cudaGetSymbolAddress((void**)&wc1, g_wcat1);
    cudaGetSymbolAddress((void**)&wc2, g_wcat2);
    cudaGetSymbolAddress((void**)&wc3, g_wcat3);
    cudaGetSymbolAddress((void**)&qh, g_qh);
    cudaGetSymbolAddress((void**)&ql, g_ql);
    cudaGetSymbolAddress((void**)&kh, g_kh);
    cudaGetSymbolAddress((void**)&vth, g_vth);

    cudaFuncSetAttribute(gemm_qkv, cudaFuncAttributeMaxDynamicSharedMemorySize, GEMM_SMEM);
    cudaFuncSetAttribute(gemm_out, cudaFuncAttributeMaxDynamicSharedMemorySize, GEMM_SMEM);
    cudaFuncSetAttribute(attn_mma, cudaFuncAttributeMaxDynamicSharedMemorySize, ATTN2_SMEM);

    rope_table<<<(S_ * 64) / 256, 256>>>();

    split_all<<<40960, 256>>>(query, key, value, wq, wk, wv, wo,
                              ac0, ac1, ac2, wc0, wc1, wc2, wc3);

    gemm_qkv<<<dim3(D_/128, M_/128, 3), 256, GEMM_SMEM>>>(
        ac0, ac1, ac2, wc0, wc1, wc2, bq, bk, bv, qh, ql, kh, vth);

    attn_mma<<<dim3(S_ / 128, BH_), 256, ATTN2_SMEM>>>(qh, ql, kh, vth, ac0);

    gemm_out<<<dim3(D_/128, M_/128), 256, GEMM_SMEM>>>(ac0, wc3, bo, out);
}

// round 14
// speedup vs baseline: 1.5520x; 1.0903x over previous
#include <cuda_runtime.h>
#include <cuda_fp16.h>
#include <math.h>
#include <stdint.h>

#define B_  2
#define S_  2048
#define D_  2048
#define H_  16
#define DK_ 128
#define M_  (B_*S_)   // 4096
#define BH_ (B_*H_)   // 32
#define K2_ 4096      // activations: [hi | lo] fp16
#define KW_ 2048      // weights: single fp16

// ---------------- scratch (device globals; no allocs allowed) ----------------
__device__ __half g_acat0[M_*K2_];  // query split / attn-out split
__device__ __half g_acat1[M_*K2_];  // key split
__device__ __half g_acat2[M_*K2_];  // value split
__device__ __half g_wcat0[D_*KW_];  // wq (single)
__device__ __half g_wcat1[D_*KW_];  // wk
__device__ __half g_wcat2[D_*KW_];  // wv
__device__ __half g_wcat3[D_*KW_];  // wo
__device__ float g_cos[S_*64];
__device__ float g_sin[S_*64];
__device__ __half g_qh[BH_*S_*DK_];                    // q single
__device__ __half g_kh[BH_*S_*DK_];                    // k single
__device__ __half g_vth[BH_*DK_*S_];                   // v single, [bh][d][s]

__device__ __forceinline__ uint32_t smem_u32(const void* p) {
    uint32_t a;
    asm("{ .reg .u64 t; cvta.to.shared.u64 t, %1; cvt.u32.u64 %0, t; }" : "=r"(a) : "l"(p));
    return a;
}

#define LDSM4(r0,r1,r2,r3, addr) \
    asm volatile("ldmatrix.sync.aligned.m8n8.x4.shared.b16 {%0,%1,%2,%3}, [%4];" \
        : "=r"(r0), "=r"(r1), "=r"(r2), "=r"(r3) : "r"(addr))

#define MMA16816(d, a, b0v, b1v) \
    asm volatile("mma.sync.aligned.m16n8k16.row.col.f32.f16.f16.f32 " \
        "{%0,%1,%2,%3}, {%4,%5,%6,%7}, {%8,%9}, {%0,%1,%2,%3};" \
        : "+f"((d)[0]), "+f"((d)[1]), "+f"((d)[2]), "+f"((d)[3]) \
        : "r"((a)[0]), "r"((a)[1]), "r"((a)[2]), "r"((a)[3]), "r"(b0v), "r"(b1v))

#define CPA16(dst, src) \
    asm volatile("cp.async.cg.shared.global [%0], [%1], 16;" :: "r"(dst), "l"(src))

// ---------------- splits: activations hi/lo, weights single ----------------
__device__ __forceinline__ void split_act(
    const float* __restrict__ x, __half* __restrict__ out, int lb)
{
    int i4 = (lb * 256 + threadIdx.x) * 4;
    int r = i4 >> 11, c = i4 & 2047;
    float4 v = *(const float4*)(x + i4);
    __half2 H01 = __floats2half2_rn(v.x, v.y);
    __half2 H23 = __floats2half2_rn(v.z, v.w);
    __half2 L01 = __floats2half2_rn(v.x - __half2float(__low2half(H01)),
                                    v.y - __half2float(__high2half(H01)));
    __half2 L23 = __floats2half2_rn(v.z - __half2float(__low2half(H23)),
                                    v.w - __half2float(__high2half(H23)));
    __half* row = out + (size_t)r * K2_ + c;
    *(__half2*)(row)            = H01;
    *(__half2*)(row + 2)        = H23;
    *(__half2*)(row + 2048)     = L01;
    *(__half2*)(row + 2048 + 2) = L23;
}

__device__ __forceinline__ void split_w(
    const float* __restrict__ x, __half* __restrict__ out, int lb)
{
    int i4 = (lb * 256 + threadIdx.x) * 4;
    float4 v = *(const float4*)(x + i4);
    *(__half2*)(out + i4)     = __floats2half2_rn(v.x, v.y);
    *(__half2*)(out + i4 + 2) = __floats2half2_rn(v.z, v.w);
}

// blocks: 3x8192 activations, then 4x4096 weights
__global__ __launch_bounds__(256) void split_all(
    const float* q, const float* k, const float* v,
    const float* wq, const float* wk, const float* wv, const float* wo,
    __half* a0, __half* a1, __half* a2,
    __half* w0, __half* w1, __half* w2, __half* w3)
{
    int bx = blockIdx.x;
    if (bx < 8192)        split_act(q, a0, bx);
    else if (bx < 16384)  split_act(k, a1, bx - 8192);
    else if (bx < 24576)  split_act(v, a2, bx - 16384);
    else {
        int t = bx - 24576, z = t >> 12, lb = t & 4095;
        const float* x = z == 0 ? wq : (z == 1 ? wk : (z == 2 ? wv : wo));
        __half* o = z == 0 ? w0 : (z == 1 ? w1 : (z == 2 ? w2 : w3));
        split_w(x, o, lb);
    }
}

// ---------------- RoPE table ----------------
__global__ __launch_bounds__(256) void rope_table()
{
    int idx = blockIdx.x * blockDim.x + threadIdx.x;
    if (idx >= S_ * 64) return;
    int i = idx & 63;
    int s = idx >> 6;
    float inv = powf(10000.f, -(float)(2 * i) / 128.f);
    float ph  = (float)s * inv;
    g_cos[idx] = cosf(ph);
    g_sin[idx] = sinf(ph);
}

// ---------------- 2-term fp16 GEMM: C = (Ahi+Alo) * W^T + bias ----------------
// modes: 0 fp32 out; 2 transpose single(v); 3 rope single(q,k)
#define BUF_B 8192
#define STAGE_B (3*BUF_B)             // Ahi, Alo, W = 24576 B
#define NSTG 3
#define GEMM_SMEM (NSTG*STAGE_B)      // 73728 B
#define NCH2 64
#define SWX(r, cI) ((uint32_t)((r)*64 + ((((cI) ^ (((r)>>1)&3)) & 3) << 4)))
#define LDE 133

__device__ __forceinline__ void gemm_body(
    const __half* __restrict__ A, const __half* __restrict__ Wt,
    const float* __restrict__ bias, int mode, float* __restrict__ C,
    __half* __restrict__ bho)
{
    extern __shared__ __half sm[];
    const int tid = threadIdx.x;
    const int lane = tid & 31, w = tid >> 5;
    const int wm = (w >> 2) << 6;
    const int wn = (w & 3) << 5;
    const int m0 = blockIdx.y << 7, n0 = blockIdx.x << 7;

    const __half* Ag = A  + (size_t)m0 * K2_;
    const __half* Wg = Wt + (size_t)n0 * KW_;

    float acc[4][4][4];
#pragma unroll
    for (int mi = 0; mi < 4; mi++)
#pragma unroll
        for (int ni = 0; ni < 4; ni++)
#pragma unroll
            for (int j = 0; j < 4; j++) acc[mi][ni][j] = 0.f;

    const int r0 = tid >> 2,        cI0 = tid & 3;
    const int r1 = (tid >> 2) + 64, cI1 = tid & 3;
    const uint32_t so0 = SWX(r0, cI0), so1 = SWX(r1, cI1);
    const int e0 = cI0 << 3, e1 = cI1 << 3;
#define LOAD_CHUNK2(stage, chunk) do {                                           \
    uint32_t sb = smem_u32((const char*)sm + (stage) * STAGE_B);                 \
    const size_t off = (size_t)(chunk) * 32;                                     \
    CPA16(sb + so0,            Ag + (size_t)r0*K2_ + off + e0);                  \
    CPA16(sb + so1,            Ag + (size_t)r1*K2_ + off + e1);                  \
    CPA16(sb + BUF_B + so0,    Ag + (size_t)r0*K2_ + 2048 + off + e0);           \
    CPA16(sb + BUF_B + so1,    Ag + (size_t)r1*K2_ + 2048 + off + e1);           \
    CPA16(sb + 2*BUF_B + so0,  Wg + (size_t)r0*KW_ + off + e0);                  \
    CPA16(sb + 2*BUF_B + so1,  Wg + (size_t)r1*KW_ + off + e1);                  \
    asm volatile("cp.async.commit_group;" ::: "memory");                         \
} while (0)

    LOAD_CHUNK2(0, 0);
    LOAD_CHUNK2(1, 1);

    for (int c = 0; c < NCH2; c++) {
        const int s = c % NSTG;
        if (c + 1 < NCH2) {
            asm volatile("cp.async.wait_group 1;" ::: "memory");
        } else {
            asm volatile("cp.async.wait_group 0;" ::: "memory");
        }
        __syncthreads();

        if (c + 2 < NCH2) LOAD_CHUNK2((c + 2) % NSTG, c + 2);

        const uint32_t sb = smem_u32((const char*)sm + s * STAGE_B);
#pragma unroll
        for (int ks = 0; ks < 2; ks++) {
            const int kbase = ks << 1;
            uint32_t ah[4][4], al[4][4];
#pragma unroll
            for (int mi = 0; mi < 4; mi++) {
                int r = wm + (mi << 4) + (lane & 15);
                int cI = kbase + (lane >> 4);
                uint32_t off = SWX(r, cI);
                LDSM4(ah[mi][0], ah[mi][1], ah[mi][2], ah[mi][3], sb + off);
                LDSM4(al[mi][0], al[mi][1], al[mi][2], al[mi][3], sb + BUF_B + off);
            }
            uint32_t bw[4][2];
#pragma unroll
            for (int nb = 0; nb < 2; nb++) {
                int r = wn + (nb << 4) + (lane & 7) + (((lane >> 4) & 1) << 3);
                int cI = kbase + ((lane >> 3) & 1);
                uint32_t off = SWX(r, cI);
                LDSM4(bw[nb*2][0], bw[nb*2][1], bw[nb*2+1][0], bw[nb*2+1][1],
                      sb + 2*BUF_B + off);
            }
#pragma unroll
            for (int mi = 0; mi < 4; mi++)
#pragma unroll
                for (int ni = 0; ni < 4; ni++) {
                    MMA16816(acc[mi][ni], ah[mi], bw[ni][0], bw[ni][1]);
                    MMA16816(acc[mi][ni], al[mi], bw[ni][0], bw[ni][1]);
                }
        }
    }

    if (mode == 0) {
#pragma unroll
        for (int mi = 0; mi < 4; mi++) {
#pragma unroll
            for (int half = 0; half < 2; half++) {
                int m = m0 + wm + (mi << 4) + (lane >> 2) + (half << 3);
#pragma unroll
                for (int ni = 0; ni < 4; ni++) {
                    int n = n0 + wn + (ni << 3) + ((lane & 3) << 1);
                    float2 o;
                    o.x = acc[mi][ni][half*2+0] + bias[n];
                    o.y = acc[mi][ni][half*2+1] + bias[n+1];
                    *(float2*)(C + (size_t)m * D_ + n) = o;
                }
            }
        }
        return;
    }

    // staged fp32 tile in smem, then fused epilogue
    __syncthreads();
    float* sf = (float*)sm;
#pragma unroll
    for (int mi = 0; mi < 4; mi++)
#pragma unroll
        for (int half = 0; half < 2; half++) {
            int ml = wm + (mi << 4) + (lane >> 2) + (half << 3);
#pragma unroll
            for (int ni = 0; ni < 4; ni++) {
                int nl = wn + (ni << 3) + ((lane & 3) << 1);
                sf[ml*LDE + nl]     = acc[mi][ni][half*2+0] + bias[n0 + nl];
                sf[ml*LDE + nl + 1] = acc[mi][ni][half*2+1] + bias[n0 + nl + 1];
            }
        }
    __syncthreads();

    const int b  = m0 >> 11;
    const int s0 = m0 & (S_ - 1);
    const int h  = n0 >> 7;
    const int bh = b * H_ + h;

    if (mode == 3) {
        // rope, single fp16 -> [bh][s][128]
        for (int idx = tid; idx < 128 * 64; idx += 256) {
            int r = idx >> 6, i = idx & 63;
            int s = s0 + r;
            float x1 = sf[r*LDE + i], x2 = sf[r*LDE + 64 + i];
            float cc = g_cos[(s << 6) + i], sn = g_sin[(s << 6) + i];
            size_t o = (((size_t)bh * S_ + s) << 7) + i;
            bho[o]      = __float2half_rn(x1 * cc - x2 * sn);
            bho[o + 64] = __float2half_rn(x2 * cc + x1 * sn);
        }
    } else {
        // mode 2: transpose, single fp16 -> [bh][d][s]
        for (int idx = tid; idx < 128 * 128; idx += 256) {
            int d = idx >> 7, sl = idx & 127;
            bho[((size_t)bh * DK_ + d) * S_ + s0 + sl] = __float2half_rn(sf[sl*LDE + d]);
        }
    }
}

__global__ __launch_bounds__(256, 2) void gemm_qkv(
    const __half* a0, const __half* a1, const __half* a2,
    const __half* w0, const __half* w1, const __half* w2,
    const float* b0, const float* b1, const float* b2,
    __half* qh, __half* kh, __half* vth)
{
    int z = blockIdx.z;
    const __half* A = z == 0 ? a0 : (z == 1 ? a1 : a2);
    const __half* W = z == 0 ? w0 : (z == 1 ? w1 : w2);
    const float* bias = z == 0 ? b0 : (z == 1 ? b1 : b2);
    if (z == 0)      gemm_body(A, W, bias, 3, (float*)0, qh);
    else if (z == 1) gemm_body(A, W, bias, 3, (float*)0, kh);
    else             gemm_body(A, W, bias, 2, (float*)0, vth);
}

__global__ __launch_bounds__(256, 2) void gemm_out(
    const __half* A, const __half* W, const float* bias, float* C)
{
    gemm_body(A, W, bias, 0, C, (__half*)0);
}

// ---------------- fp16 tensor-core causal flash attention (all-single) -------
// BR=128 (8 warps x 16 rows, 256 thr), BC=64, 2-stage KV.
// Q,K,V,P all single fp16; fp32 accumulate.
#define QLD 136
#define VLD 72
#define oQ  0
#define oKV 17408
#define stKV 17920          // K 64x136=8704 + V 128x72=9216 (elems)
#define ATTN2_SMEM ((oKV + 2*stKV)*2)   // 106496 B

__global__ __launch_bounds__(256, 1) void attn_mma(
    const __half* __restrict__ gqh, const __half* __restrict__ gkh,
    const __half* __restrict__ gvh, __half* __restrict__ acat)
{
    extern __shared__ __half smb[];
    const uint32_t usm = smem_u32(smb);
    const int tid = threadIdx.x;
    const int lane = tid & 31, w = tid >> 5;
    const int wrow = w << 4;
    const int qt = gridDim.x - 1 - blockIdx.x;
    const int bh = blockIdx.y;
    const int b  = bh >> 4, h = bh & 15;
    const int nblk = 2 * qt + 2;
    const float SCL2 = 0.12751743f;     // 1/sqrt(128) * log2(e)

    const size_t qbase = ((size_t)bh * S_ + (size_t)qt * 128) << 7;

    {
#pragma unroll
        for (int i = 0; i < 8; i++) {
            int ch = tid + (i << 8);
            int r = ch >> 4, c8 = (ch & 15) << 3;
            CPA16(usm + (uint32_t)(oQ + r * QLD + c8) * 2, gqh + qbase + ((size_t)r << 7) + c8);
        }
    }
#define LOAD_KV(stage, jb) do {                                                      \
    uint32_t kvb = oKV + (stage) * stKV;                                             \
    size_t kbase = ((size_t)bh * S_ + (size_t)(jb) * 64) << 7;                       \
    _Pragma("unroll")                                                                \
    for (int i = 0; i < 4; i++) {                                                    \
        int ch = tid + (i << 8);                                                     \
        int r = ch >> 4, c8 = (ch & 15) << 3;                                        \
        CPA16(usm + (kvb + r * QLD + c8) * 2, gkh + kbase + ((size_t)r << 7) + c8);  \
    }                                                                                \
    size_t vbase = ((size_t)bh * DK_) * S_ + (size_t)(jb) * 64;                      \
    _Pragma("unroll")                                                                \
    for (int i = 0; i < 4; i++) {                                                    \
        int ch = tid + (i << 8);                                                     \
        int r = ch >> 3, c8 = (ch & 7) << 3;                                         \
        CPA16(usm + (kvb + 8704 + r * VLD + c8) * 2, gvh + vbase + (size_t)r * S_ + c8); \
    }                                                                                \
    asm volatile("cp.async.commit_group;" ::: "memory");                             \
} while (0)

    LOAD_KV(0, 0);
    LOAD_KV(1, 1);

    float oa[16][4];
#pragma unroll
    for (int nt = 0; nt < 16; nt++)
#pragma unroll
        for (int j = 0; j < 4; j++) oa[nt][j] = 0.f;
    float m0r = -1e30f, m1r = -1e30f, l0r = 0.f, l1r = 0.f;

    const int grow0 = qt * 128 + wrow + (lane >> 2);
    const int grow1 = grow0 + 8;

    for (int jb = 0; jb < nblk; jb++) {
        const int st = jb & 1;
        if (jb + 1 < nblk) {
            asm volatile("cp.async.wait_group 1;" ::: "memory");
        } else {
            asm volatile("cp.async.wait_group 0;" ::: "memory");
        }
        __syncthreads();

        const uint32_t kvb = oKV + st * stKV;

        // ---- S = Q K^T : single-term, per-warp 16x64
        float sa[8][4];
#pragma unroll
        for (int nt = 0; nt < 8; nt++)
#pragma unroll
            for (int j = 0; j < 4; j++) sa[nt][j] = 0.f;

#pragma unroll
        for (int kt = 0; kt < 8; kt++) {
            const int kc = kt << 4;
            uint32_t aq[4];
            {
                int r = wrow + (lane & 15);
                int cc = kc + ((lane >> 4) << 3);
                LDSM4(aq[0], aq[1], aq[2], aq[3], usm + (uint32_t)(oQ + r * QLD + cc) * 2);
            }
#pragma unroll
            for (int ntp = 0; ntp < 4; ntp++) {
                int r = (ntp << 4) + (lane & 7) + (((lane >> 4) & 1) << 3);
                int cc = kc + (((lane >> 3) & 1) << 3);
                uint32_t bk[4];
                LDSM4(bk[0], bk[1], bk[2], bk[3], usm + (kvb + r * QLD + cc) * 2);
#pragma unroll
                for (int t = 0; t < 2; t++)
                    MMA16816(sa[(ntp << 1) + t], aq, bk[2*t], bk[2*t+1]);
            }
        }

        const bool needmask = (jb >= 2 * qt);
#pragma unroll
        for (int nt = 0; nt < 8; nt++) {
            int cb = jb * 64 + (nt << 3) + ((lane & 3) << 1);
#pragma unroll
            for (int j = 0; j < 4; j++) {
                float x = sa[nt][j] * SCL2;
                if (needmask) {
                    int col = cb + (j & 1);
                    int row = (j < 2) ? grow0 : grow1;
                    if (col > row) x = -1e30f;
                }
                sa[nt][j] = x;
            }
        }

        float rm0 = -1e30f, rm1 = -1e30f;
#pragma unroll
        for (int nt = 0; nt < 8; nt++) {
            rm0 = fmaxf(rm0, fmaxf(sa[nt][0], sa[nt][1]));
            rm1 = fmaxf(rm1, fmaxf(sa[nt][2], sa[nt][3]));
        }
        rm0 = fmaxf(rm0, __shfl_xor_sync(0xffffffffu, rm0, 1));
        rm0 = fmaxf(rm0, __shfl_xor_sync(0xffffffffu, rm0, 2));
        rm1 = fmaxf(rm1, __shfl_xor_sync(0xffffffffu, rm1, 1));
        rm1 = fmaxf(rm1, __shfl_xor_sync(0xffffffffu, rm1, 2));
        float mn0 = fmaxf(m0r, rm0), mn1 = fmaxf(m1r, rm1);
        float al0 = exp2f(m0r - mn0), al1 = exp2f(m1r - mn1);
        m0r = mn0; m1r = mn1;

        float rs0 = 0.f, rs1 = 0.f;
#pragma unroll
        for (int nt = 0; nt < 8; nt++) {
            float p0 = exp2f(sa[nt][0] - mn0);
            float p1 = exp2f(sa[nt][1] - mn0);
            float p2 = exp2f(sa[nt][2] - mn1);
            float p3 = exp2f(sa[nt][3] - mn1);
            sa[nt][0] = p0; sa[nt][1] = p1; sa[nt][2] = p2; sa[nt][3] = p3;
            rs0 += p0 + p1; rs1 += p2 + p3;
        }
        rs0 += __shfl_xor_sync(0xffffffffu, rs0, 1);
        rs0 += __shfl_xor_sync(0xffffffffu, rs0, 2);
        rs1 += __shfl_xor_sync(0xffffffffu, rs1, 1);
        rs1 += __shfl_xor_sync(0xffffffffu, rs1, 2);
        l0r = l0r * al0 + rs0;
        l1r = l1r * al1 + rs1;

#pragma unroll
        for (int nt = 0; nt < 16; nt++) {
            oa[nt][0] *= al0; oa[nt][1] *= al0;
            oa[nt][2] *= al1; oa[nt][3] *= al1;
        }

        // ---- O += P V : p single fp16
#pragma unroll
        for (int kt2 = 0; kt2 < 4; kt2++) {
            const int t0 = kt2 << 1, t1 = t0 + 1;
            uint32_t pa[4];
            {
                __half2 hh;
                hh = __floats2half2_rn(sa[t0][0], sa[t0][1]); pa[0] = *(uint32_t*)&hh;
                hh = __floats2half2_rn(sa[t0][2], sa[t0][3]); pa[1] = *(uint32_t*)&hh;
                hh = __floats2half2_rn(sa[t1][0], sa[t1][1]); pa[2] = *(uint32_t*)&hh;
                hh = __floats2half2_rn(sa[t1][2], sa[t1][3]); pa[3] = *(uint32_t*)&hh;
            }
            const int cv = (kt2 << 4) + (((lane >> 3) & 1) << 3);
#pragma unroll
            for (int ntp = 0; ntp < 8; ntp++) {
                int r = (ntp << 4) + (lane & 7) + (((lane >> 4) & 1) << 3);
                uint32_t vv[4];
                LDSM4(vv[0], vv[1], vv[2], vv[3], usm + (kvb + 8704 + r * VLD + cv) * 2);
#pragma unroll
                for (int t = 0; t < 2; t++)
                    MMA16816(oa[(ntp << 1) + t], pa, vv[2*t], vv[2*t+1]);
            }
        }

        __syncthreads();
        if (jb + 2 < nblk) LOAD_KV(st, jb + 2);
    }

    // ---- epilogue: O /= l, hi/lo fp16 split into acat [m][4096]
    float inv0 = 1.f / l0r, inv1 = 1.f / l1r;
    int srow0 = qt * 128 + wrow + (lane >> 2);
    int mrow0 = b * S_ + srow0;
    __half* a0 = acat + (size_t)mrow0 * K2_ + (h << 7);
    __half* a1 = a0 + (size_t)8 * K2_;
#pragma unroll
    for (int nt = 0; nt < 16; nt++) {
        int cb = (nt << 3) + ((lane & 3) << 1);
        float v00 = oa[nt][0] * inv0, v01 = oa[nt][1] * inv0;
        float v10 = oa[nt][2] * inv1, v11 = oa[nt][3] * inv1;
        __half2 h0 = __floats2half2_rn(v00, v01);
        __half2 l0p = __floats2half2_rn(v00 - __half2float(__low2half(h0)),
                                        v01 - __half2float(__high2half(h0)));
        __half2 h1 = __floats2half2_rn(v10, v11);
        __half2 l1p = __floats2half2_rn(v10 - __half2float(__low2half(h1)),
                                        v11 - __half2float(__high2half(h1)));
        *(__half2*)(a0 + cb)        = h0;
        *(__half2*)(a0 + 2048 + cb) = l0p;
        *(__half2*)(a1 + cb)        = h1;
        *(__half2*)(a1 + 2048 + cb) = l1p;
    }
}

// ---------------- launch ----------------
extern "C" void kernel_launch(void* const* d_in, const int* in_sizes, int n_in,
                              void* d_out, int out_size)
{
    const float* query = (const float*)d_in[0];
    const float* key   = (const float*)d_in[1];
    const float* value = (const float*)d_in[2];
    const float* wq = (const float*)d_in[4];
    const float* bq = (const float*)d_in[5];
    const float* wk = (const float*)d_in[6];
    const float* bk = (const float*)d_in[7];
    const float* wv = (const float*)d_in[8];
    const float* bv = (const float*)d_in[9];
    const float* wo = (const float*)d_in[10];
    const float* bo = (const float*)d_in[11];
    float* out = (float*)d_out;

    __half *ac0, *ac1, *ac2, *wc0, *wc1, *wc2, *wc3;
    __half *qh, *kh, *vth;
    cudaGetSymbolAddress((void**)&ac0, g_acat0);
    cudaGetSymbolAddress((void**)&ac1, g_acat1);
    cudaGetSymbolAddress((void**)&ac2, g_acat2);
    cudaGetSymbolAddress((void**)&wc0, g_wcat0);
    cudaGetSymbolAddress((void**)&wc1, g_wcat1);
    cudaGetSymbolAddress((void**)&wc2, g_wcat2);
    cudaGetSymbolAddress((void**)&wc3, g_wcat3);
    cudaGetSymbolAddress((void**)&qh, g_qh);
    cudaGetSymbolAddress((void**)&kh, g_kh);
    cudaGetSymbolAddress((void**)&vth, g_vth);

    cudaFuncSetAttribute(gemm_qkv, cudaFuncAttributeMaxDynamicSharedMemorySize, GEMM_SMEM);
    cudaFuncSetAttribute(gemm_out, cudaFuncAttributeMaxDynamicSharedMemorySize, GEMM_SMEM);
    cudaFuncSetAttribute(attn_mma, cudaFuncAttributeMaxDynamicSharedMemorySize, ATTN2_SMEM);

    rope_table<<<(S_ * 64) / 256, 256>>>();

    split_all<<<40960, 256>>>(query, key, value, wq, wk, wv, wo,
                              ac0, ac1, ac2, wc0, wc1, wc2, wc3);

    gemm_qkv<<<dim3(D_/128, M_/128, 3), 256, GEMM_SMEM>>>(
        ac0, ac1, ac2, wc0, wc1, wc2, bq, bk, bv, qh, kh, vth);

    attn_mma<<<dim3(S_ / 128, BH_), 256, ATTN2_SMEM>>>(qh, kh, vth, ac0);

    gemm_out<<<dim3(D_/128, M_/128), 256, GEMM_SMEM>>>(ac0, wc3, bo, out);
}

// round 16
// speedup vs baseline: 2.2913x; 1.4764x over previous
#include <cuda_runtime.h>
#include <cuda_fp16.h>
#include <math.h>
#include <stdint.h>

#define B_  2
#define S_  2048
#define D_  2048
#define H_  16
#define DK_ 128
#define M_  (B_*S_)   // 4096
#define BH_ (B_*H_)   // 32
#define KW_ 2048      // single fp16 everywhere

// ---------------- scratch (device globals; no allocs allowed) ----------------
__device__ __half g_acat0[M_*KW_];  // query / attn-out
__device__ __half g_acat1[M_*KW_];  // key
__device__ __half g_acat2[M_*KW_];  // value
__device__ __half g_wcat0[D_*KW_];  // wq
__device__ __half g_wcat1[D_*KW_];  // wk
__device__ __half g_wcat2[D_*KW_];  // wv
__device__ __half g_wcat3[D_*KW_];  // wo
__device__ float g_cos[S_*64];
__device__ float g_sin[S_*64];
__device__ __half g_qh[BH_*S_*DK_];
__device__ __half g_kh[BH_*S_*DK_];
__device__ __half g_vth[BH_*DK_*S_];   // [bh][d][s]

__device__ __forceinline__ uint32_t smem_u32(const void* p) {
    uint32_t a;
    asm("{ .reg .u64 t; cvta.to.shared.u64 t, %1; cvt.u32.u64 %0, t; }" : "=r"(a) : "l"(p));
    return a;
}

#define LDSM4(r0,r1,r2,r3, addr) \
    asm volatile("ldmatrix.sync.aligned.m8n8.x4.shared.b16 {%0,%1,%2,%3}, [%4];" \
        : "=r"(r0), "=r"(r1), "=r"(r2), "=r"(r3) : "r"(addr))

#define MMA16816(d, a, b0v, b1v) \
    asm volatile("mma.sync.aligned.m16n8k16.row.col.f32.f16.f16.f32 " \
        "{%0,%1,%2,%3}, {%4,%5,%6,%7}, {%8,%9}, {%0,%1,%2,%3};" \
        : "+f"((d)[0]), "+f"((d)[1]), "+f"((d)[2]), "+f"((d)[3]) \
        : "r"((a)[0]), "r"((a)[1]), "r"((a)[2]), "r"((a)[3]), "r"(b0v), "r"(b1v))

#define CPA16(dst, src) \
    asm volatile("cp.async.cg.shared.global [%0], [%1], 16;" :: "r"(dst), "l"(src))

// ---------------- fp32 -> fp16 convert (7 tensors, one launch) ----------------
__device__ __forceinline__ void cvt_body(
    const float* __restrict__ x, __half* __restrict__ out, int lb)
{
    int i4 = (lb * 256 + threadIdx.x) * 4;
    float4 v = *(const float4*)(x + i4);
    *(__half2*)(out + i4)     = __floats2half2_rn(v.x, v.y);
    *(__half2*)(out + i4 + 2) = __floats2half2_rn(v.z, v.w);
}

// blocks: 3x8192 activations, then 4x4096 weights
__global__ __launch_bounds__(256) void split_all(
    const float* q, const float* k, const float* v,
    const float* wq, const float* wk, const float* wv, const float* wo,
    __half* a0, __half* a1, __half* a2,
    __half* w0, __half* w1, __half* w2, __half* w3)
{
    int bx = blockIdx.x;
    if (bx < 8192)        cvt_body(q, a0, bx);
    else if (bx < 16384)  cvt_body(k, a1, bx - 8192);
    else if (bx < 24576)  cvt_body(v, a2, bx - 16384);
    else {
        int t = bx - 24576, z = t >> 12, lb = t & 4095;
        const float* x = z == 0 ? wq : (z == 1 ? wk : (z == 2 ? wv : wo));
        __half* o = z == 0 ? w0 : (z == 1 ? w1 : (z == 2 ? w2 : w3));
        cvt_body(x, o, lb);
    }
}

// ---------------- RoPE table ----------------
__global__ __launch_bounds__(256) void rope_table()
{
    int idx = blockIdx.x * blockDim.x + threadIdx.x;
    if (idx >= S_ * 64) return;
    int i = idx & 63;
    int s = idx >> 6;
    float inv = powf(10000.f, -(float)(2 * i) / 128.f);
    float ph  = (float)s * inv;
    g_cos[idx] = cosf(ph);
    g_sin[idx] = sinf(ph);
}

// ---------------- single-term fp16 GEMM: C = A * W^T + bias ----------------
// modes: 0 fp32 out; 2 transpose single(v); 3 rope single(q,k)
#define BUF_B 8192
#define STAGE_B (2*BUF_B)             // A, W = 16384 B
#define NSTG 3
#define LDE 133
// smem must cover BOTH the 3-stage ring (49152 B) and the fp32 staging
// epilogue tile 128*LDE*4 = 68096 B. (This was the round-15 OOB crash.)
#define GEMM_SMEM 69632
#define NCH2 64
#define SWX(r, cI) ((uint32_t)((r)*64 + ((((cI) ^ (((r)>>1)&3)) & 3) << 4)))

__device__ __forceinline__ void gemm_body(
    const __half* __restrict__ A, const __half* __restrict__ Wt,
    const float* __restrict__ bias, int mode, float* __restrict__ C,
    __half* __restrict__ bho)
{
    extern __shared__ __half sm[];
    const int tid = threadIdx.x;
    const int lane = tid & 31, w = tid >> 5;
    const int wm = (w >> 2) << 6;
    const int wn = (w & 3) << 5;
    const int m0 = blockIdx.y << 7, n0 = blockIdx.x << 7;

    const __half* Ag = A  + (size_t)m0 * KW_;
    const __half* Wg = Wt + (size_t)n0 * KW_;

    float acc[4][4][4];
#pragma unroll
    for (int mi = 0; mi < 4; mi++)
#pragma unroll
        for (int ni = 0; ni < 4; ni++)
#pragma unroll
            for (int j = 0; j < 4; j++) acc[mi][ni][j] = 0.f;

    const int r0 = tid >> 2,        cI0 = tid & 3;
    const int r1 = (tid >> 2) + 64, cI1 = tid & 3;
    const uint32_t so0 = SWX(r0, cI0), so1 = SWX(r1, cI1);
    const int e0 = cI0 << 3, e1 = cI1 << 3;
#define LOAD_CHUNK2(stage, chunk) do {                                           \
    uint32_t sb = smem_u32((const char*)sm + (stage) * STAGE_B);                 \
    const size_t off = (size_t)(chunk) * 32;                                     \
    CPA16(sb + so0,            Ag + (size_t)r0*KW_ + off + e0);                  \
    CPA16(sb + so1,            Ag + (size_t)r1*KW_ + off + e1);                  \
    CPA16(sb + BUF_B + so0,    Wg + (size_t)r0*KW_ + off + e0);                  \
    CPA16(sb + BUF_B + so1,    Wg + (size_t)r1*KW_ + off + e1);                  \
    asm volatile("cp.async.commit_group;" ::: "memory");                         \
} while (0)

    LOAD_CHUNK2(0, 0);
    LOAD_CHUNK2(1, 1);

    for (int c = 0; c < NCH2; c++) {
        const int s = c % NSTG;
        if (c + 1 < NCH2) {
            asm volatile("cp.async.wait_group 1;" ::: "memory");
        } else {
            asm volatile("cp.async.wait_group 0;" ::: "memory");
        }
        __syncthreads();

        if (c + 2 < NCH2) LOAD_CHUNK2((c + 2) % NSTG, c + 2);

        const uint32_t sb = smem_u32((const char*)sm + s * STAGE_B);
#pragma unroll
        for (int ks = 0; ks < 2; ks++) {
            const int kbase = ks << 1;
            uint32_t a[4][4];
#pragma unroll
            for (int mi = 0; mi < 4; mi++) {
                int r = wm + (mi << 4) + (lane & 15);
                int cI = kbase + (lane >> 4);
                uint32_t off = SWX(r, cI);
                LDSM4(a[mi][0], a[mi][1], a[mi][2], a[mi][3], sb + off);
            }
            uint32_t bw[4][2];
#pragma unroll
            for (int nb = 0; nb < 2; nb++) {
                int r = wn + (nb << 4) + (lane & 7) + (((lane >> 4) & 1) << 3);
                int cI = kbase + ((lane >> 3) & 1);
                uint32_t off = SWX(r, cI);
                LDSM4(bw[nb*2][0], bw[nb*2][1], bw[nb*2+1][0], bw[nb*2+1][1],
                      sb + BUF_B + off);
            }
#pragma unroll
            for (int mi = 0; mi < 4; mi++)
#pragma unroll
                for (int ni = 0; ni < 4; ni++)
                    MMA16816(acc[mi][ni], a[mi], bw[ni][0], bw[ni][1]);
        }
    }

    if (mode == 0) {
#pragma unroll
        for (int mi = 0; mi < 4; mi++) {
#pragma unroll
            for (int half = 0; half < 2; half++) {
                int m = m0 + wm + (mi << 4) + (lane >> 2) + (half << 3);
#pragma unroll
                for (int ni = 0; ni < 4; ni++) {
                    int n = n0 + wn + (ni << 3) + ((lane & 3) << 1);
                    float2 o;
                    o.x = acc[mi][ni][half*2+0] + bias[n];
                    o.y = acc[mi][ni][half*2+1] + bias[n+1];
                    *(float2*)(C + (size_t)m * D_ + n) = o;
                }
            }
        }
        return;
    }

    // staged fp32 tile in smem, then fused epilogue
    __syncthreads();
    float* sf = (float*)sm;
#pragma unroll
    for (int mi = 0; mi < 4; mi++)
#pragma unroll
        for (int half = 0; half < 2; half++) {
            int ml = wm + (mi << 4) + (lane >> 2) + (half << 3);
#pragma unroll
            for (int ni = 0; ni < 4; ni++) {
                int nl = wn + (ni << 3) + ((lane & 3) << 1);
                sf[ml*LDE + nl]     = acc[mi][ni][half*2+0] + bias[n0 + nl];
                sf[ml*LDE + nl + 1] = acc[mi][ni][half*2+1] + bias[n0 + nl + 1];
            }
        }
    __syncthreads();

    const int b  = m0 >> 11;
    const int s0 = m0 & (S_ - 1);
    const int h  = n0 >> 7;
    const int bh = b * H_ + h;

    if (mode == 3) {
        // rope, single fp16 -> [bh][s][128]
        for (int idx = tid; idx < 128 * 64; idx += 256) {
            int r = idx >> 6, i = idx & 63;
            int s = s0 + r;
            float x1 = sf[r*LDE + i], x2 = sf[r*LDE + 64 + i];
            float cc = g_cos[(s << 6) + i], sn = g_sin[(s << 6) + i];
            size_t o = (((size_t)bh * S_ + s) << 7) + i;
            bho[o]      = __float2half_rn(x1 * cc - x2 * sn);
            bho[o + 64] = __float2half_rn(x2 * cc + x1 * sn);
        }
    } else {
        // mode 2: transpose, single fp16 -> [bh][d][s]
        for (int idx = tid; idx < 128 * 128; idx += 256) {
            int d = idx >> 7, sl = idx & 127;
            bho[((size_t)bh * DK_ + d) * S_ + s0 + sl] = __float2half_rn(sf[sl*LDE + d]);
        }
    }
}

__global__ __launch_bounds__(256, 2) void gemm_qkv(
    const __half* a0, const __half* a1, const __half* a2,
    const __half* w0, const __half* w1, const __half* w2,
    const float* b0, const float* b1, const float* b2,
    __half* qh, __half* kh, __half* vth)
{
    int z = blockIdx.z;
    const __half* A = z == 0 ? a0 : (z == 1 ? a1 : a2);
    const __half* W = z == 0 ? w0 : (z == 1 ? w1 : w2);
    const float* bias = z == 0 ? b0 : (z == 1 ? b1 : b2);
    if (z == 0)      gemm_body(A, W, bias, 3, (float*)0, qh);
    else if (z == 1) gemm_body(A, W, bias, 3, (float*)0, kh);
    else             gemm_body(A, W, bias, 2, (float*)0, vth);
}

__global__ __launch_bounds__(256, 2) void gemm_out(
    const __half* A, const __half* W, const float* bias, float* C)
{
    gemm_body(A, W, bias, 0, C, (__half*)0);
}

// ---------------- fp16 tensor-core causal flash attention (all-single) -------
// BR=128 (8 warps x 16 rows, 256 thr), BC=64, 2-stage KV.
#define QLD 136
#define VLD 72
#define oQ  0
#define oKV 17408
#define stKV 17920          // K 64x136=8704 + V 128x72=9216 (elems)
#define ATTN2_SMEM ((oKV + 2*stKV)*2)   // 106496 B

__global__ __launch_bounds__(256, 1) void attn_mma(
    const __half* __restrict__ gqh, const __half* __restrict__ gkh,
    const __half* __restrict__ gvh, __half* __restrict__ acat)
{
    extern __shared__ __half smb[];
    const uint32_t usm = smem_u32(smb);
    const int tid = threadIdx.x;
    const int lane = tid & 31, w = tid >> 5;
    const int wrow = w << 4;
    const int qt = gridDim.x - 1 - blockIdx.x;
    const int bh = blockIdx.y;
    const int b  = bh >> 4, h = bh & 15;
    const int nblk = 2 * qt + 2;
    const float SCL2 = 0.12751743f;     // 1/sqrt(128) * log2(e)

    const size_t qbase = ((size_t)bh * S_ + (size_t)qt * 128) << 7;

    {
#pragma unroll
        for (int i = 0; i < 8; i++) {
            int ch = tid + (i << 8);
            int r = ch >> 4, c8 = (ch & 15) << 3;
            CPA16(usm + (uint32_t)(oQ + r * QLD + c8) * 2, gqh + qbase + ((size_t)r << 7) + c8);
        }
    }
#define LOAD_KV(stage, jb) do {                                                      \
    uint32_t kvb = oKV + (stage) * stKV;                                             \
    size_t kbase = ((size_t)bh * S_ + (size_t)(jb) * 64) << 7;                       \
    _Pragma("unroll")                                                                \
    for (int i = 0; i < 4; i++) {                                                    \
        int ch = tid + (i << 8);                                                     \
        int r = ch >> 4, c8 = (ch & 15) << 3;                                        \
        CPA16(usm + (kvb + r * QLD + c8) * 2, gkh + kbase + ((size_t)r << 7) + c8);  \
    }                                                                                \
    size_t vbase = ((size_t)bh * DK_) * S_ + (size_t)(jb) * 64;                      \
    _Pragma("unroll")                                                                \
    for (int i = 0; i < 4; i++) {                                                    \
        int ch = tid + (i << 8);                                                     \
        int r = ch >> 3, c8 = (ch & 7) << 3;                                         \
        CPA16(usm + (kvb + 8704 + r * VLD + c8) * 2, gvh + vbase + (size_t)r * S_ + c8); \
    }                                                                                \
    asm volatile("cp.async.commit_group;" ::: "memory");                             \
} while (0)

    LOAD_KV(0, 0);
    LOAD_KV(1, 1);

    float oa[16][4];
#pragma unroll
    for (int nt = 0; nt < 16; nt++)
#pragma unroll
        for (int j = 0; j < 4; j++) oa[nt][j] = 0.f;
    float m0r = -1e30f, m1r = -1e30f, l0r = 0.f, l1r = 0.f;

    const int grow0 = qt * 128 + wrow + (lane >> 2);
    const int grow1 = grow0 + 8;

    for (int jb = 0; jb < nblk; jb++) {
        const int st = jb & 1;
        if (jb + 1 < nblk) {
            asm volatile("cp.async.wait_group 1;" ::: "memory");
        } else {
            asm volatile("cp.async.wait_group 0;" ::: "memory");
        }
        __syncthreads();

        const uint32_t kvb = oKV + st * stKV;

        // ---- S = Q K^T
        float sa[8][4];
#pragma unroll
        for (int nt = 0; nt < 8; nt++)
#pragma unroll
            for (int j = 0; j < 4; j++) sa[nt][j] = 0.f;

#pragma unroll
        for (int kt = 0; kt < 8; kt++) {
            const int kc = kt << 4;
            uint32_t aq[4];
            {
                int r = wrow + (lane & 15);
                int cc = kc + ((lane >> 4) << 3);
                LDSM4(aq[0], aq[1], aq[2], aq[3], usm + (uint32_t)(oQ + r * QLD + cc) * 2);
            }
#pragma unroll
            for (int ntp = 0; ntp < 4; ntp++) {
                int r = (ntp << 4) + (lane & 7) + (((lane >> 4) & 1) << 3);
                int cc = kc + (((lane >> 3) & 1) << 3);
                uint32_t bk[4];
                LDSM4(bk[0], bk[1], bk[2], bk[3], usm + (kvb + r * QLD + cc) * 2);
#pragma unroll
                for (int t = 0; t < 2; t++)
                    MMA16816(sa[(ntp << 1) + t], aq, bk[2*t], bk[2*t+1]);
            }
        }

        const bool needmask = (jb >= 2 * qt);
#pragma unroll
        for (int nt = 0; nt < 8; nt++) {
            int cb = jb * 64 + (nt << 3) + ((lane & 3) << 1);
#pragma unroll
            for (int j = 0; j < 4; j++) {
                float x = sa[nt][j] * SCL2;
                if (needmask) {
                    int col = cb + (j & 1);
                    int row = (j < 2) ? grow0 : grow1;
                    if (col > row) x = -1e30f;
                }
                sa[nt][j] = x;
            }
        }

        float rm0 = -1e30f, rm1 = -1e30f;
#pragma unroll
        for (int nt = 0; nt < 8; nt++) {
            rm0 = fmaxf(rm0, fmaxf(sa[nt][0], sa[nt][1]));
            rm1 = fmaxf(rm1, fmaxf(sa[nt][2], sa[nt][3]));
        }
        rm0 = fmaxf(rm0, __shfl_xor_sync(0xffffffffu, rm0, 1));
        rm0 = fmaxf(rm0, __shfl_xor_sync(0xffffffffu, rm0, 2));
        rm1 = fmaxf(rm1, __shfl_xor_sync(0xffffffffu, rm1, 1));
        rm1 = fmaxf(rm1, __shfl_xor_sync(0xffffffffu, rm1, 2));
        float mn0 = fmaxf(m0r, rm0), mn1 = fmaxf(m1r, rm1);
        float al0 = exp2f(m0r - mn0), al1 = exp2f(m1r - mn1);
        m0r = mn0; m1r = mn1;

        float rs0 = 0.f, rs1 = 0.f;
#pragma unroll
        for (int nt = 0; nt < 8; nt++) {
            float p0 = exp2f(sa[nt][0] - mn0);
            float p1 = exp2f(sa[nt][1] - mn0);
            float p2 = exp2f(sa[nt][2] - mn1);
            float p3 = exp2f(sa[nt][3] - mn1);
            sa[nt][0] = p0; sa[nt][1] = p1; sa[nt][2] = p2; sa[nt][3] = p3;
            rs0 += p0 + p1; rs1 += p2 + p3;
        }
        rs0 += __shfl_xor_sync(0xffffffffu, rs0, 1);
        rs0 += __shfl_xor_sync(0xffffffffu, rs0, 2);
        rs1 += __shfl_xor_sync(0xffffffffu, rs1, 1);
        rs1 += __shfl_xor_sync(0xffffffffu, rs1, 2);
        l0r = l0r * al0 + rs0;
        l1r = l1r * al1 + rs1;

#pragma unroll
        for (int nt = 0; nt < 16; nt++) {
            oa[nt][0] *= al0; oa[nt][1] *= al0;
            oa[nt][2] *= al1; oa[nt][3] *= al1;
        }

        // ---- O += P V
#pragma unroll
        for (int kt2 = 0; kt2 < 4; kt2++) {
            const int t0 = kt2 << 1, t1 = t0 + 1;
            uint32_t pa[4];
            {
                __half2 hh;
                hh = __floats2half2_rn(sa[t0][0], sa[t0][1]); pa[0] = *(uint32_t*)&hh;
                hh = __floats2half2_rn(sa[t0][2], sa[t0][3]); pa[1] = *(uint32_t*)&hh;
                hh = __floats2half2_rn(sa[t1][0], sa[t1][1]); pa[2] = *(uint32_t*)&hh;
                hh = __floats2half2_rn(sa[t1][2], sa[t1][3]); pa[3] = *(uint32_t*)&hh;
            }
            const int cv = (kt2 << 4) + (((lane >> 3) & 1) << 3);
#pragma unroll
            for (int ntp = 0; ntp < 8; ntp++) {
                int r = (ntp << 4) + (lane & 7) + (((lane >> 4) & 1) << 3);
                uint32_t vv[4];
                LDSM4(vv[0], vv[1], vv[2], vv[3], usm + (kvb + 8704 + r * VLD + cv) * 2);
#pragma unroll
                for (int t = 0; t < 2; t++)
                    MMA16816(oa[(ntp << 1) + t], pa, vv[2*t], vv[2*t+1]);
            }
        }

        __syncthreads();
        if (jb + 2 < nblk) LOAD_KV(st, jb + 2);
    }

    // ---- epilogue: O /= l, single fp16 into acat [m][2048]
    float inv0 = 1.f / l0r, inv1 = 1.f / l1r;
    int srow0 = qt * 128 + wrow + (lane >> 2);
    int mrow0 = b * S_ + srow0;
    __half* a0 = acat + (size_t)mrow0 * KW_ + (h << 7);
    __half* a1 = a0 + (size_t)8 * KW_;
#pragma unroll
    for (int nt = 0; nt < 16; nt++) {
        int cb = (nt << 3) + ((lane & 3) << 1);
        *(__half2*)(a0 + cb) = __floats2half2_rn(oa[nt][0] * inv0, oa[nt][1] * inv0);
        *(__half2*)(a1 + cb) = __floats2half2_rn(oa[nt][2] * inv1, oa[nt][3] * inv1);
    }
}

// ---------------- launch ----------------
extern "C" void kernel_launch(void* const* d_in, const int* in_sizes, int n_in,
                              void* d_out, int out_size)
{
    const float* query = (const float*)d_in[0];
    const float* key   = (const float*)d_in[1];
    const float* value = (const float*)d_in[2];
    const float* wq = (const float*)d_in[4];
    const float* bq = (const float*)d_in[5];
    const float* wk = (const float*)d_in[6];
    const float* bk = (const float*)d_in[7];
    const float* wv = (const float*)d_in[8];
    const float* bv = (const float*)d_in[9];
    const float* wo = (const float*)d_in[10];
    const float* bo = (const float*)d_in[11];
    float* out = (float*)d_out;

    __half *ac0, *ac1, *ac2, *wc0, *wc1, *wc2, *wc3;
    __half *qh, *kh, *vth;
    cudaGetSymbolAddress((void**)&ac0, g_acat0);
    cudaGetSymbolAddress((void**)&ac1, g_acat1);
    cudaGetSymbolAddress((void**)&ac2, g_acat2);
    cudaGetSymbolAddress((void**)&wc0, g_wcat0);
    cudaGetSymbolAddress((void**)&wc1, g_wcat1);
    cudaGetSymbolAddress((void**)&wc2, g_wcat2);
    cudaGetSymbolAddress((void**)&wc3, g_wcat3);
    cudaGetSymbolAddress((void**)&qh, g_qh);
    cudaGetSymbolAddress((void**)&kh, g_kh);
    cudaGetSymbolAddress((void**)&vth, g_vth);

    cudaFuncSetAttribute(gemm_qkv, cudaFuncAttributeMaxDynamicSharedMemorySize, GEMM_SMEM);
    cudaFuncSetAttribute(gemm_out, cudaFuncAttributeMaxDynamicSharedMemorySize, GEMM_SMEM);
    cudaFuncSetAttribute(attn_mma, cudaFuncAttributeMaxDynamicSharedMemorySize, ATTN2_SMEM);

    rope_table<<<(S_ * 64) / 256, 256>>>();

    split_all<<<40960, 256>>>(query, key, value, wq, wk, wv, wo,
                              ac0, ac1, ac2, wc0, wc1, wc2, wc3);

    gemm_qkv<<<dim3(D_/128, M_/128, 3), 256, GEMM_SMEM>>>(
        ac0, ac1, ac2, wc0, wc1, wc2, bq, bk, bv, qh, kh, vth);

    attn_mma<<<dim3(S_ / 128, BH_), 256, ATTN2_SMEM>>>(qh, kh, vth, ac0);

    gemm_out<<<dim3(D_/128, M_/128), 256, GEMM_SMEM>>>(ac0, wc3, bo, out);
}